// round 8
// baseline (speedup 1.0000x reference)
#include <cuda_runtime.h>
#include <cuda_bf16.h>
#include <stdint.h>

#define B_  2
#define S_  2048
#define D_  1024
#define H_  16
#define DH_ 64
#define NE_ (B_ * S_ * D_)
#define NKB (S_ / 64)
#define NW_ (D_ * D_)

// Scratch (allocation-free): bf16 hi/lo planes packed 2-per-u32.
__device__ uint32_t g_Qh[NE_ / 2], g_Ql[NE_ / 2];   // proj Q, pre-scaled
__device__ uint32_t g_Kh[NE_ / 2], g_Kl[NE_ / 2];   // proj K
__device__ uint32_t g_Vh[NE_ / 2], g_Vl[NE_ / 2];   // proj V transposed [b][h][dh][s]
__device__ uint32_t g_AOh[NE_ / 2], g_AOl[NE_ / 2]; // attention output planes
__device__ uint32_t g_Xqh[NE_ / 2], g_Xql[NE_ / 2];
__device__ uint32_t g_Xkh[NE_ / 2], g_Xkl[NE_ / 2];
__device__ uint32_t g_Xvh[NE_ / 2], g_Xvl[NE_ / 2];
__device__ uint32_t g_Wqh[NW_ / 2], g_Wql[NW_ / 2];
__device__ uint32_t g_Wkh[NW_ / 2], g_Wkl[NW_ / 2];
__device__ uint32_t g_Wvh[NW_ / 2], g_Wvl[NW_ / 2];
__device__ uint32_t g_Woh[NW_ / 2], g_Wol[NW_ / 2];

// (1/8) * log2(e): folds softmax exp -> exp2
#define QSCALE 0.1803368801111204f

// ---------------------------------------------------------------------------
__device__ __forceinline__ void split2(float x, float y, uint32_t& hi, uint32_t& lo)
{
    __nv_bfloat162 h = __floats2bfloat162_rn(x, y);
    float rx = x - __bfloat162float(h.x);
    float ry = y - __bfloat162float(h.y);
    __nv_bfloat162 l = __floats2bfloat162_rn(rx, ry);
    hi = *reinterpret_cast<uint32_t*>(&h);
    lo = *reinterpret_cast<uint32_t*>(&l);
}

__device__ __forceinline__ void mma_bf16(float4& d,
    uint32_t a0, uint32_t a1, uint32_t a2, uint32_t a3,
    uint32_t b0, uint32_t b1)
{
    asm volatile(
        "mma.sync.aligned.m16n8k16.row.col.f32.bf16.bf16.f32 "
        "{%0,%1,%2,%3},{%4,%5,%6,%7},{%8,%9},{%0,%1,%2,%3};"
        : "+f"(d.x), "+f"(d.y), "+f"(d.z), "+f"(d.w)
        : "r"(a0), "r"(a1), "r"(a2), "r"(a3), "r"(b0), "r"(b1));
}

__device__ __forceinline__ void ldsm_x4(uint32_t& r0, uint32_t& r1,
                                        uint32_t& r2, uint32_t& r3, uint32_t addr)
{
    asm volatile("ldmatrix.sync.aligned.m8n8.x4.shared.b16 {%0,%1,%2,%3}, [%4];"
                 : "=r"(r0), "=r"(r1), "=r"(r2), "=r"(r3) : "r"(addr));
}

__device__ __forceinline__ void cp16(uint32_t smaddr, const void* g)
{
    asm volatile("cp.async.cg.shared.global [%0], [%1], 16;" :: "r"(smaddr), "l"(g));
}
__device__ __forceinline__ void cp_commit()
{
    asm volatile("cp.async.commit_group;" ::: "memory");
}

// ---------------------------------------------------------------------------
// ONE fused split pass.
// ---------------------------------------------------------------------------
__global__ __launch_bounds__(256) void split_all(
    const float* __restrict__ q, const float* __restrict__ k, const float* __restrict__ v,
    const float* __restrict__ wq, const float* __restrict__ wk,
    const float* __restrict__ wv, const float* __restrict__ wo)
{
    const int bid = blockIdx.x;
    const float* src;
    uint32_t *hi, *lo;
    int i;
    if (bid < 12288) {
        int seg = bid >> 12;
        i = (bid & 4095) * 256 + threadIdx.x;
        if (seg == 0)      { src = q; hi = g_Xqh; lo = g_Xql; }
        else if (seg == 1) { src = k; hi = g_Xkh; lo = g_Xkl; }
        else               { src = v; hi = g_Xvh; lo = g_Xvl; }
    } else {
        int seg = (bid - 12288) >> 10;
        i = ((bid - 12288) & 1023) * 256 + threadIdx.x;
        if (seg == 0)      { src = wq; hi = g_Wqh; lo = g_Wql; }
        else if (seg == 1) { src = wk; hi = g_Wkh; lo = g_Wkl; }
        else if (seg == 2) { src = wv; hi = g_Wvh; lo = g_Wvl; }
        else               { src = wo; hi = g_Woh; lo = g_Wol; }
    }
    float4 val = ((const float4*)src)[i];
    uint32_t h0, l0, h1, l1;
    split2(val.x, val.y, h0, l0);
    split2(val.z, val.w, h1, l1);
    ((uint2*)hi)[i] = make_uint2(h0, h1);
    ((uint2*)lo)[i] = make_uint2(l0, l1);
}

// ---------------------------------------------------------------------------
// bf16x3 GEMM core: BM=128, BN=128, BK=16/stage, 4 stages, prefetch depth 3,
// ONE __syncthreads per k-iter. 256 thr, 8 warps (4m x 2n), warp tile 32x64.
// Stage: 4 planes x 128 rows x 12 u32 (8 data + 4 pad) = 6144 u32 = 24576 B.
// Dyn smem: 4 x 24576 = 98304 B (2 CTAs/SM).
// ---------------------------------------------------------------------------
#define SSTG_B  24576u
#define SA_LO   (1536u * 4u)
#define SW_HI   (3072u * 4u)
#define SW_LO   (4608u * 4u)
#define GNT     (D_ / 16)     // 64 k-iterations

__device__ __forceinline__ void gemm_core(
    const uint32_t* __restrict__ Ah, const uint32_t* __restrict__ Al,
    const uint32_t* __restrict__ Wh, const uint32_t* __restrict__ Wl,
    const float* __restrict__ bias,
    float* __restrict__ Cf, uint32_t* __restrict__ Ch, uint32_t* __restrict__ Cl,
    int mode, uint32_t sb)
{
    const int tid  = threadIdx.x;
    const int lane = tid & 31;
    const int wid  = tid >> 5;
    const int wm   = wid & 3;
    const int wn   = wid >> 2;
    const int r    = lane >> 2;
    const int c    = lane & 3;

    const int m_base = blockIdx.y * 128;
    const int n_base = blockIdx.x * 128;
    const int KW = D_ >> 1;

    const int lrA = (lane & 7) + (((lane >> 3) & 1) << 3);
    const int lcA = (lane >> 4) * 4;
    const int lrB = (lane & 7) + ((lane >> 4) << 3);
    const int lcB = ((lane >> 3) & 1) * 4;

    // loader: 1 cp16 per plane per thread (128 rows x 2 chunks = 256)
    const int lrow = tid >> 1, lcg = (tid & 1) * 4;
    const uint32_t lso = (uint32_t)(lrow * 12 + lcg) * 4u;

    auto prefetch = [&](int ktile) {
        uint32_t base = sb + (uint32_t)(ktile & 3) * SSTG_B;
        int ktw = ktile * 8;
        size_t ga = (size_t)(m_base + lrow) * KW + ktw + lcg;
        size_t gw = (size_t)(n_base + lrow) * KW + ktw + lcg;
        cp16(base + lso,         Ah + ga);
        cp16(base + SA_LO + lso, Al + ga);
        cp16(base + SW_HI + lso, Wh + gw);
        cp16(base + SW_LO + lso, Wl + gw);
        cp_commit();
    };

    float4 acc[2][8];
#pragma unroll
    for (int i = 0; i < 2; i++)
#pragma unroll
        for (int j = 0; j < 8; j++) acc[i][j] = make_float4(0.f, 0.f, 0.f, 0.f);

    prefetch(0); prefetch(1); prefetch(2);

    for (int kt = 0; kt < GNT; kt++) {
        asm volatile("cp.async.wait_group 2;" ::: "memory");
        __syncthreads();
        if (kt + 3 < GNT) prefetch(kt + 3);
        else cp_commit();   // empty group keeps wait_group 2 uniform

        uint32_t base = sb + (uint32_t)(kt & 3) * SSTG_B;

        uint32_t ah[2][4], al[2][4];
#pragma unroll
        for (int mt = 0; mt < 2; mt++) {
            uint32_t o = (uint32_t)((wm * 32 + mt * 16 + lrA) * 12 + lcA) * 4u;
            ldsm_x4(ah[mt][0], ah[mt][1], ah[mt][2], ah[mt][3], base + o);
            ldsm_x4(al[mt][0], al[mt][1], al[mt][2], al[mt][3], base + SA_LO + o);
        }
#pragma unroll
        for (int ntp = 0; ntp < 4; ntp++) {
            uint32_t o = (uint32_t)((wn * 64 + ntp * 16 + lrB) * 12 + lcB) * 4u;
            uint32_t bh0, bh1, bh2, bh3, bl0, bl1, bl2, bl3;
            ldsm_x4(bh0, bh1, bh2, bh3, base + SW_HI + o);
            ldsm_x4(bl0, bl1, bl2, bl3, base + SW_LO + o);
#pragma unroll
            for (int mt = 0; mt < 2; mt++) {
                mma_bf16(acc[mt][2 * ntp],     ah[mt][0], ah[mt][1], ah[mt][2], ah[mt][3], bh0, bh1);
                mma_bf16(acc[mt][2 * ntp],     ah[mt][0], ah[mt][1], ah[mt][2], ah[mt][3], bl0, bl1);
                mma_bf16(acc[mt][2 * ntp],     al[mt][0], al[mt][1], al[mt][2], al[mt][3], bh0, bh1);
                mma_bf16(acc[mt][2 * ntp + 1], ah[mt][0], ah[mt][1], ah[mt][2], ah[mt][3], bh2, bh3);
                mma_bf16(acc[mt][2 * ntp + 1], ah[mt][0], ah[mt][1], ah[mt][2], ah[mt][3], bl2, bl3);
                mma_bf16(acc[mt][2 * ntp + 1], al[mt][0], al[mt][1], al[mt][2], al[mt][3], bh2, bh3);
            }
        }
    }

    // epilogue
#pragma unroll
    for (int mt = 0; mt < 2; mt++) {
#pragma unroll
        for (int nt = 0; nt < 8; nt++) {
            int gm0 = m_base + wm * 32 + mt * 16 + r;
            int gm1 = gm0 + 8;
            int gn  = n_base + wn * 64 + nt * 8 + c * 2;
            float b0v = bias[gn], b1v = bias[gn + 1];
            float f00 = acc[mt][nt].x + b0v, f01 = acc[mt][nt].y + b1v;
            float f10 = acc[mt][nt].z + b0v, f11 = acc[mt][nt].w + b1v;
            if (mode == 1) { f00 *= QSCALE; f01 *= QSCALE; f10 *= QSCALE; f11 *= QSCALE; }

            if (mode == 0) {
                *(float2*)(Cf + (size_t)gm0 * D_ + gn) = make_float2(f00, f01);
                *(float2*)(Cf + (size_t)gm1 * D_ + gn) = make_float2(f10, f11);
            } else if (mode == 1 || mode == 2) {
                uint32_t h0, l0, h1, l1;
                split2(f00, f01, h0, l0);
                split2(f10, f11, h1, l1);
                Ch[(size_t)gm0 * 512 + gn / 2] = h0;
                Cl[(size_t)gm0 * 512 + gn / 2] = l0;
                Ch[(size_t)gm1 * 512 + gn / 2] = h1;
                Cl[(size_t)gm1 * 512 + gn / 2] = l1;
            } else {
                __nv_bfloat16* Chb = (__nv_bfloat16*)Ch;
                __nv_bfloat16* Clb = (__nv_bfloat16*)Cl;
                float fv[2][2] = {{f00, f01}, {f10, f11}};
                int gms[2] = {gm0, gm1};
#pragma unroll
                for (int i = 0; i < 2; i++)
#pragma unroll
                    for (int j = 0; j < 2; j++) {
                        int m = gms[i], n = gn + j;
                        int bb = m >> 11, s = m & 2047;
                        int hh = n >> 6, dh = n & 63;
                        size_t idx = (((size_t)(bb * H_ + hh) * DH_ + dh) * S_) + s;
                        __nv_bfloat16 hv = __float2bfloat16_rn(fv[i][j]);
                        float lvf = fv[i][j] - __bfloat162float(hv);
                        Chb[idx] = hv;
                        Clb[idx] = __float2bfloat16_rn(lvf);
                    }
            }
        }
    }
}

__global__ __launch_bounds__(256, 2) void gemm_qkv(
    const float* __restrict__ b_q, const float* __restrict__ b_k,
    const float* __restrict__ b_v)
{
    extern __shared__ uint32_t sg[];
    const uint32_t sb = (uint32_t)__cvta_generic_to_shared(sg);
    const int z = blockIdx.z;
    if (z == 0)
        gemm_core(g_Xqh, g_Xql, g_Wqh, g_Wql, b_q, nullptr, g_Qh, g_Ql, 1, sb);
    else if (z == 1)
        gemm_core(g_Xkh, g_Xkl, g_Wkh, g_Wkl, b_k, nullptr, g_Kh, g_Kl, 2, sb);
    else
        gemm_core(g_Xvh, g_Xvl, g_Wvh, g_Wvl, b_v, nullptr, g_Vh, g_Vl, 3, sb);
}

__global__ __launch_bounds__(256, 2) void gemm_out(
    const float* __restrict__ b_o, float* __restrict__ out)
{
    extern __shared__ uint32_t sg[];
    const uint32_t sb = (uint32_t)__cvta_generic_to_shared(sg);
    gemm_core(g_AOh, g_AOl, g_Woh, g_Wol, b_o, out, nullptr, nullptr, 0, sb);
}

// ---------------------------------------------------------------------------
// Flash attention, mma bf16x3, exp2 softmax. 3-stage cp.async pipeline,
// prefetch depth 2, ONE sync per key-block. 4 warps, 32 q-rows/warp.
// Stage: 4 planes x 64 x 36 u32 = 9216 u32 = 36864 B; 3 stages = 110592 B.
// ---------------------------------------------------------------------------
#define ASTG_B 36864u

__global__ __launch_bounds__(128, 2) void attn_mma(
    const uint32_t* __restrict__ Qh, const uint32_t* __restrict__ Ql,
    const uint32_t* __restrict__ Kh, const uint32_t* __restrict__ Kl,
    const uint32_t* __restrict__ Vh, const uint32_t* __restrict__ Vl,
    uint32_t* __restrict__ AOh, uint32_t* __restrict__ AOl)
{
    extern __shared__ uint32_t smu[];
    const int tid  = threadIdx.x;
    const int lane = tid & 31;
    const int wid  = tid >> 5;
    const int r    = lane >> 2;
    const int c    = lane & 3;
    const int h    = blockIdx.y;
    const int b    = blockIdx.z;
    const int q0   = blockIdx.x * 128 + wid * 32;

    const size_t qk_base = ((size_t)b * S_ * D_ + h * DH_) / 2;
    const size_t v_base  = ((size_t)(b * H_ + h) * DH_ * S_) / 2;
    const uint32_t* Qh32 = Qh + qk_base;
    const uint32_t* Ql32 = Ql + qk_base;
    const uint32_t* Kh32 = Kh + qk_base;
    const uint32_t* Kl32 = Kl + qk_base;
    const uint32_t* Vh32 = Vh + v_base;
    const uint32_t* Vl32 = Vl + v_base;

    const uint32_t sbase = (uint32_t)__cvta_generic_to_shared(smu);
    const int lr  = (lane & 7) + ((lane >> 4) << 3);
    const int lc4 = ((lane >> 3) & 1) * 4;
    const uint32_t laddr = (uint32_t)(lr * 36 + lc4) * 4;

    uint32_t qh[2][4][4], ql[2][4][4];
#pragma unroll
    for (int mt = 0; mt < 2; mt++) {
        int rb = q0 + mt * 16;
#pragma unroll
        for (int kt = 0; kt < 4; kt++) {
            qh[mt][kt][0] = Qh32[(size_t)(rb + r) * 512 + kt * 8 + c];
            qh[mt][kt][1] = Qh32[(size_t)(rb + 8 + r) * 512 + kt * 8 + c];
            qh[mt][kt][2] = Qh32[(size_t)(rb + r) * 512 + kt * 8 + c + 4];
            qh[mt][kt][3] = Qh32[(size_t)(rb + 8 + r) * 512 + kt * 8 + c + 4];
            ql[mt][kt][0] = Ql32[(size_t)(rb + r) * 512 + kt * 8 + c];
            ql[mt][kt][1] = Ql32[(size_t)(rb + 8 + r) * 512 + kt * 8 + c];
            ql[mt][kt][2] = Ql32[(size_t)(rb + r) * 512 + kt * 8 + c + 4];
            ql[mt][kt][3] = Ql32[(size_t)(rb + 8 + r) * 512 + kt * 8 + c + 4];
        }
    }

    float4 oacc[2][8];
#pragma unroll
    for (int mt = 0; mt < 2; mt++)
#pragma unroll
        for (int j = 0; j < 8; j++) oacc[mt][j] = make_float4(0.f, 0.f, 0.f, 0.f);
    float mi[2][2], li[2][2];
#pragma unroll
    for (int mt = 0; mt < 2; mt++) { mi[mt][0] = mi[mt][1] = -1e30f; li[mt][0] = li[mt][1] = 0.f; }

    auto prefetch = [&](int kb) {
        uint32_t bufb = sbase + (uint32_t)(kb % 3) * ASTG_B;
#pragma unroll
        for (int t = 0; t < 4; t++) {
            int i = tid + t * 128;
            int row = i >> 3, col = (i & 7) * 4;
            uint32_t off = (uint32_t)(row * 36 + col) * 4;
            size_t kg = (size_t)(kb * 64 + row) * 512 + col;
            size_t vg = (size_t)row * 1024 + kb * 32 + col;
            cp16(bufb + off,            Kh32 + kg);
            cp16(bufb + 2304 * 4 + off, Kl32 + kg);
            cp16(bufb + 4608 * 4 + off, Vh32 + vg);
            cp16(bufb + 6912 * 4 + off, Vl32 + vg);
        }
        cp_commit();
    };

    prefetch(0); prefetch(1);

    for (int kb = 0; kb < NKB; kb++) {
        asm volatile("cp.async.wait_group 1;" ::: "memory");
        __syncthreads();
        if (kb + 2 < NKB) prefetch(kb + 2);
        else cp_commit();

        uint32_t bufb = sbase + (uint32_t)(kb % 3) * ASTG_B;
        uint32_t kh_b = bufb, kl_b = bufb + 2304 * 4;
        uint32_t vh_b = bufb + 4608 * 4, vl_b = bufb + 6912 * 4;

        float4 sacc[2][8];
#pragma unroll
        for (int mt = 0; mt < 2; mt++)
#pragma unroll
            for (int nt = 0; nt < 8; nt++) sacc[mt][nt] = make_float4(0.f, 0.f, 0.f, 0.f);
#pragma unroll
        for (int ng = 0; ng < 4; ng++) {
#pragma unroll
            for (int kt = 0; kt < 4; kt++) {
                uint32_t o = laddr + (uint32_t)(ng * 576 + kt * 8) * 4;
                uint32_t h0, h1, h2, h3, l0, l1, l2, l3;
                ldsm_x4(h0, h1, h2, h3, kh_b + o);
                ldsm_x4(l0, l1, l2, l3, kl_b + o);
#pragma unroll
                for (int mt = 0; mt < 2; mt++) {
                    mma_bf16(sacc[mt][2 * ng],     qh[mt][kt][0], qh[mt][kt][1], qh[mt][kt][2], qh[mt][kt][3], h0, h1);
                    mma_bf16(sacc[mt][2 * ng],     qh[mt][kt][0], qh[mt][kt][1], qh[mt][kt][2], qh[mt][kt][3], l0, l1);
                    mma_bf16(sacc[mt][2 * ng],     ql[mt][kt][0], ql[mt][kt][1], ql[mt][kt][2], ql[mt][kt][3], h0, h1);
                    mma_bf16(sacc[mt][2 * ng + 1], qh[mt][kt][0], qh[mt][kt][1], qh[mt][kt][2], qh[mt][kt][3], h2, h3);
                    mma_bf16(sacc[mt][2 * ng + 1], qh[mt][kt][0], qh[mt][kt][1], qh[mt][kt][2], qh[mt][kt][3], l2, l3);
                    mma_bf16(sacc[mt][2 * ng + 1], ql[mt][kt][0], ql[mt][kt][1], ql[mt][kt][2], ql[mt][kt][3], h2, h3);
                }
            }
        }

        uint32_t ph[2][4][4], pl[2][4][4];
#pragma unroll
        for (int mt = 0; mt < 2; mt++) {
            float m0 = -1e30f, m1 = -1e30f;
#pragma unroll
            for (int nt = 0; nt < 8; nt++) {
                m0 = fmaxf(m0, fmaxf(sacc[mt][nt].x, sacc[mt][nt].y));
                m1 = fmaxf(m1, fmaxf(sacc[mt][nt].z, sacc[mt][nt].w));
            }
#pragma unroll
            for (int o = 1; o <= 2; o <<= 1) {
                m0 = fmaxf(m0, __shfl_xor_sync(0xffffffffu, m0, o));
                m1 = fmaxf(m1, __shfl_xor_sync(0xffffffffu, m1, o));
            }
            float mn0 = fmaxf(mi[mt][0], m0), mn1 = fmaxf(mi[mt][1], m1);
            float corr0 = exp2f(mi[mt][0] - mn0), corr1 = exp2f(mi[mt][1] - mn1);
            float rs0 = 0.f, rs1 = 0.f;
#pragma unroll
            for (int nt = 0; nt < 8; nt++) {
                sacc[mt][nt].x = exp2f(sacc[mt][nt].x - mn0);
                sacc[mt][nt].y = exp2f(sacc[mt][nt].y - mn0);
                sacc[mt][nt].z = exp2f(sacc[mt][nt].z - mn1);
                sacc[mt][nt].w = exp2f(sacc[mt][nt].w - mn1);
                rs0 += sacc[mt][nt].x + sacc[mt][nt].y;
                rs1 += sacc[mt][nt].z + sacc[mt][nt].w;
            }
#pragma unroll
            for (int o = 1; o <= 2; o <<= 1) {
                rs0 += __shfl_xor_sync(0xffffffffu, rs0, o);
                rs1 += __shfl_xor_sync(0xffffffffu, rs1, o);
            }
            li[mt][0] = li[mt][0] * corr0 + rs0;
            li[mt][1] = li[mt][1] * corr1 + rs1;
            mi[mt][0] = mn0; mi[mt][1] = mn1;
#pragma unroll
            for (int j = 0; j < 8; j++) {
                oacc[mt][j].x *= corr0; oacc[mt][j].y *= corr0;
                oacc[mt][j].z *= corr1; oacc[mt][j].w *= corr1;
            }
#pragma unroll
            for (int t = 0; t < 4; t++) {
                split2(sacc[mt][2 * t].x,     sacc[mt][2 * t].y,     ph[mt][t][0], pl[mt][t][0]);
                split2(sacc[mt][2 * t].z,     sacc[mt][2 * t].w,     ph[mt][t][1], pl[mt][t][1]);
                split2(sacc[mt][2 * t + 1].x, sacc[mt][2 * t + 1].y, ph[mt][t][2], pl[mt][t][2]);
                split2(sacc[mt][2 * t + 1].z, sacc[mt][2 * t + 1].w, ph[mt][t][3], pl[mt][t][3]);
            }
        }

#pragma unroll
        for (int jg = 0; jg < 4; jg++) {
#pragma unroll
            for (int kt = 0; kt < 4; kt++) {
                uint32_t o = laddr + (uint32_t)(jg * 576 + kt * 8) * 4;
                uint32_t h0, h1, h2, h3, l0, l1, l2, l3;
                ldsm_x4(h0, h1, h2, h3, vh_b + o);
                ldsm_x4(l0, l1, l2, l3, vl_b + o);
#pragma unroll
                for (int mt = 0; mt < 2; mt++) {
                    mma_bf16(oacc[mt][2 * jg],     ph[mt][kt][0], ph[mt][kt][1], ph[mt][kt][2], ph[mt][kt][3], h0, h1);
                    mma_bf16(oacc[mt][2 * jg],     ph[mt][kt][0], ph[mt][kt][1], ph[mt][kt][2], ph[mt][kt][3], l0, l1);
                    mma_bf16(oacc[mt][2 * jg],     pl[mt][kt][0], pl[mt][kt][1], pl[mt][kt][2], pl[mt][kt][3], h0, h1);
                    mma_bf16(oacc[mt][2 * jg + 1], ph[mt][kt][0], ph[mt][kt][1], ph[mt][kt][2], ph[mt][kt][3], h2, h3);
                    mma_bf16(oacc[mt][2 * jg + 1], ph[mt][kt][0], ph[mt][kt][1], ph[mt][kt][2], ph[mt][kt][3], l2, l3);
                    mma_bf16(oacc[mt][2 * jg + 1], pl[mt][kt][0], pl[mt][kt][1], pl[mt][kt][2], pl[mt][kt][3], h2, h3);
                }
            }
        }
    }

#pragma unroll
    for (int mt = 0; mt < 2; mt++) {
        float inv0 = 1.f / li[mt][0], inv1 = 1.f / li[mt][1];
        const size_t row0 = ((size_t)b * S_ + q0 + mt * 16 + r) * 512;
        const size_t row1 = row0 + 8 * 512;
#pragma unroll
        for (int j = 0; j < 8; j++) {
            int w = h * 32 + j * 4 + c;
            uint32_t hw, lw;
            split2(oacc[mt][j].x * inv0, oacc[mt][j].y * inv0, hw, lw);
            AOh[row0 + w] = hw; AOl[row0 + w] = lw;
            split2(oacc[mt][j].z * inv1, oacc[mt][j].w * inv1, hw, lw);
            AOh[row1 + w] = hw; AOl[row1 + w] = lw;
        }
    }
}

// ---------------------------------------------------------------------------
extern "C" void kernel_launch(void* const* d_in, const int* in_sizes, int n_in,
                              void* d_out, int out_size)
{
    const float* queries = (const float*)d_in[0];
    const float* keys    = (const float*)d_in[1];
    const float* values  = (const float*)d_in[2];
    const float* W_q = (const float*)d_in[3];
    const float* b_q = (const float*)d_in[4];
    const float* W_k = (const float*)d_in[5];
    const float* b_k = (const float*)d_in[6];
    const float* W_v = (const float*)d_in[7];
    const float* b_v = (const float*)d_in[8];
    const float* W_o = (const float*)d_in[9];
    const float* b_o = (const float*)d_in[10];
    float* out = (float*)d_out;

    uint32_t *Qh, *Ql, *Kh, *Kl, *Vh, *Vl, *AOh, *AOl;
    cudaGetSymbolAddress((void**)&Qh, g_Qh);
    cudaGetSymbolAddress((void**)&Ql, g_Ql);
    cudaGetSymbolAddress((void**)&Kh, g_Kh);
    cudaGetSymbolAddress((void**)&Kl, g_Kl);
    cudaGetSymbolAddress((void**)&Vh, g_Vh);
    cudaGetSymbolAddress((void**)&Vl, g_Vl);
    cudaGetSymbolAddress((void**)&AOh, g_AOh);
    cudaGetSymbolAddress((void**)&AOl, g_AOl);

    const int gsmem = 4 * SSTG_B;     // 98304
    cudaFuncSetAttribute(gemm_qkv, cudaFuncAttributeMaxDynamicSharedMemorySize, gsmem);
    cudaFuncSetAttribute(gemm_out, cudaFuncAttributeMaxDynamicSharedMemorySize, gsmem);
    const int asmem = 3 * ASTG_B;     // 110592
    cudaFuncSetAttribute(attn_mma, cudaFuncAttributeMaxDynamicSharedMemorySize, asmem);

    split_all<<<16384, 256>>>(queries, keys, values, W_q, W_k, W_v, W_o);

    dim3 qkv_grid(D_ / 128, (B_ * S_) / 128, 3);
    gemm_qkv<<<qkv_grid, 256, gsmem>>>(b_q, b_k, b_v);

    dim3 agrid(S_ / 128, H_, B_);
    attn_mma<<<agrid, 128, asmem>>>(Qh, Ql, Kh, Kl, Vh, Vl, AOh, AOl);

    dim3 ogrid(D_ / 128, (B_ * S_) / 128);
    gemm_out<<<ogrid, 256, gsmem>>>(b_o, out);
}

// round 9
// speedup vs baseline: 1.0965x; 1.0965x over previous
#include <cuda_runtime.h>
#include <cuda_bf16.h>
#include <stdint.h>

#define B_  2
#define S_  2048
#define D_  1024
#define H_  16
#define DH_ 64
#define NE_ (B_ * S_ * D_)
#define NKB (S_ / 64)
#define NW_ (D_ * D_)

// Scratch (allocation-free): bf16 hi/lo planes packed 2-per-u32.
__device__ uint32_t g_Qh[NE_ / 2], g_Ql[NE_ / 2];   // proj Q, pre-scaled
__device__ uint32_t g_Kh[NE_ / 2], g_Kl[NE_ / 2];   // proj K
__device__ uint32_t g_Vh[NE_ / 2], g_Vl[NE_ / 2];   // proj V transposed [b][h][dh][s]
__device__ uint32_t g_AOh[NE_ / 2], g_AOl[NE_ / 2]; // attention output planes
__device__ uint32_t g_Xqh[NE_ / 2], g_Xql[NE_ / 2];
__device__ uint32_t g_Xkh[NE_ / 2], g_Xkl[NE_ / 2];
__device__ uint32_t g_Xvh[NE_ / 2], g_Xvl[NE_ / 2];
__device__ uint32_t g_Wqh[NW_ / 2], g_Wql[NW_ / 2];
__device__ uint32_t g_Wkh[NW_ / 2], g_Wkl[NW_ / 2];
__device__ uint32_t g_Wvh[NW_ / 2], g_Wvl[NW_ / 2];
__device__ uint32_t g_Woh[NW_ / 2], g_Wol[NW_ / 2];

// (1/8) * log2(e): folds softmax exp -> exp2
#define QSCALE 0.1803368801111204f

// ---------------------------------------------------------------------------
__device__ __forceinline__ void split2(float x, float y, uint32_t& hi, uint32_t& lo)
{
    __nv_bfloat162 h = __floats2bfloat162_rn(x, y);
    float rx = x - __bfloat162float(h.x);
    float ry = y - __bfloat162float(h.y);
    __nv_bfloat162 l = __floats2bfloat162_rn(rx, ry);
    hi = *reinterpret_cast<uint32_t*>(&h);
    lo = *reinterpret_cast<uint32_t*>(&l);
}

__device__ __forceinline__ void mma_bf16(float4& d,
    uint32_t a0, uint32_t a1, uint32_t a2, uint32_t a3,
    uint32_t b0, uint32_t b1)
{
    asm volatile(
        "mma.sync.aligned.m16n8k16.row.col.f32.bf16.bf16.f32 "
        "{%0,%1,%2,%3},{%4,%5,%6,%7},{%8,%9},{%0,%1,%2,%3};"
        : "+f"(d.x), "+f"(d.y), "+f"(d.z), "+f"(d.w)
        : "r"(a0), "r"(a1), "r"(a2), "r"(a3), "r"(b0), "r"(b1));
}

__device__ __forceinline__ void ldsm_x4(uint32_t& r0, uint32_t& r1,
                                        uint32_t& r2, uint32_t& r3, uint32_t addr)
{
    asm volatile("ldmatrix.sync.aligned.m8n8.x4.shared.b16 {%0,%1,%2,%3}, [%4];"
                 : "=r"(r0), "=r"(r1), "=r"(r2), "=r"(r3) : "r"(addr));
}

__device__ __forceinline__ void cp16(uint32_t smaddr, const void* g)
{
    asm volatile("cp.async.cg.shared.global [%0], [%1], 16;" :: "r"(smaddr), "l"(g));
}
__device__ __forceinline__ void cp_commit()
{
    asm volatile("cp.async.commit_group;" ::: "memory");
}

// ---------------------------------------------------------------------------
// ONE fused split pass.
// ---------------------------------------------------------------------------
__global__ __launch_bounds__(256) void split_all(
    const float* __restrict__ q, const float* __restrict__ k, const float* __restrict__ v,
    const float* __restrict__ wq, const float* __restrict__ wk,
    const float* __restrict__ wv, const float* __restrict__ wo)
{
    const int bid = blockIdx.x;
    const float* src;
    uint32_t *hi, *lo;
    int i;
    if (bid < 12288) {
        int seg = bid >> 12;
        i = (bid & 4095) * 256 + threadIdx.x;
        if (seg == 0)      { src = q; hi = g_Xqh; lo = g_Xql; }
        else if (seg == 1) { src = k; hi = g_Xkh; lo = g_Xkl; }
        else               { src = v; hi = g_Xvh; lo = g_Xvl; }
    } else {
        int seg = (bid - 12288) >> 10;
        i = ((bid - 12288) & 1023) * 256 + threadIdx.x;
        if (seg == 0)      { src = wq; hi = g_Wqh; lo = g_Wql; }
        else if (seg == 1) { src = wk; hi = g_Wkh; lo = g_Wkl; }
        else if (seg == 2) { src = wv; hi = g_Wvh; lo = g_Wvl; }
        else               { src = wo; hi = g_Woh; lo = g_Wol; }
    }
    float4 val = ((const float4*)src)[i];
    uint32_t h0, l0, h1, l1;
    split2(val.x, val.y, h0, l0);
    split2(val.z, val.w, h1, l1);
    ((uint2*)hi)[i] = make_uint2(h0, h1);
    ((uint2*)lo)[i] = make_uint2(l0, l1);
}

// ---------------------------------------------------------------------------
// bf16x3 GEMM core: BM=128, BN=128, BK=32, 2 stages, ONE __syncthreads/iter.
// 256 thr, 8 warps (4m x 2n), warp tile 32x64.
// Dyn smem: 2 stages x 10240 u32 = 81920 B (2 CTAs/SM).
// ---------------------------------------------------------------------------
#define GSTG   10240u
#define GA_LO  2560u
#define GW_HI  5120u
#define GW_LO  7680u

__device__ __forceinline__ void gemm_core(
    const uint32_t* __restrict__ Ah, const uint32_t* __restrict__ Al,
    const uint32_t* __restrict__ Wh, const uint32_t* __restrict__ Wl,
    const float* __restrict__ bias,
    float* __restrict__ Cf, uint32_t* __restrict__ Ch, uint32_t* __restrict__ Cl,
    int mode, uint32_t sb)
{
    const int tid  = threadIdx.x;
    const int lane = tid & 31;
    const int wid  = tid >> 5;
    const int wm   = wid & 3;
    const int wn   = wid >> 2;
    const int r    = lane >> 2;
    const int c    = lane & 3;

    const int m_base = blockIdx.y * 128;
    const int n_base = blockIdx.x * 128;
    const int KW = D_ >> 1;

    const int lrA = (lane & 7) + (((lane >> 3) & 1) << 3);
    const int lcA = (lane >> 4) * 4;
    const int lrB = (lane & 7) + ((lane >> 4) << 3);
    const int lcB = ((lane >> 3) & 1) * 4;

    auto prefetch = [&](int ktile) {
        uint32_t base = sb + (uint32_t)(ktile & 1) * GSTG * 4u;
        int ktw = ktile * 16;
#pragma unroll
        for (int t = 0; t < 2; t++) {
            int idx = tid + t * 256;
            int row = idx >> 2, cg = (idx & 3) * 4;
            uint32_t so = (uint32_t)(row * 20 + cg) * 4u;
            size_t ga = (size_t)(m_base + row) * KW + ktw + cg;
            size_t gw = (size_t)(n_base + row) * KW + ktw + cg;
            cp16(base + so,                Ah + ga);
            cp16(base + GA_LO * 4u + so,   Al + ga);
            cp16(base + GW_HI * 4u + so,   Wh + gw);
            cp16(base + GW_LO * 4u + so,   Wl + gw);
        }
        cp_commit();
    };

    float4 acc[2][8];
#pragma unroll
    for (int i = 0; i < 2; i++)
#pragma unroll
        for (int j = 0; j < 8; j++) acc[i][j] = make_float4(0.f, 0.f, 0.f, 0.f);

    const int NT = D_ / 32;
    prefetch(0);

    for (int kt = 0; kt < NT; kt++) {
        asm volatile("cp.async.wait_group 0;" ::: "memory");
        __syncthreads();
        // Buffer (kt+1)&1 was last read during iteration kt-1; the sync above
        // retires only after every thread finished that compute -> safe to fill.
        if (kt + 1 < NT) prefetch(kt + 1);

        uint32_t base = sb + (uint32_t)(kt & 1) * GSTG * 4u;

#pragma unroll
        for (int ks = 0; ks < 2; ks++) {
            uint32_t ah[2][4], al[2][4];
#pragma unroll
            for (int mt = 0; mt < 2; mt++) {
                uint32_t o = (uint32_t)((wm * 32 + mt * 16 + lrA) * 20 + ks * 8 + lcA) * 4u;
                ldsm_x4(ah[mt][0], ah[mt][1], ah[mt][2], ah[mt][3], base + o);
                ldsm_x4(al[mt][0], al[mt][1], al[mt][2], al[mt][3], base + GA_LO * 4u + o);
            }
#pragma unroll
            for (int ntp = 0; ntp < 4; ntp++) {
                uint32_t o = (uint32_t)((wn * 64 + ntp * 16 + lrB) * 20 + ks * 8 + lcB) * 4u;
                uint32_t bh0, bh1, bh2, bh3, bl0, bl1, bl2, bl3;
                ldsm_x4(bh0, bh1, bh2, bh3, base + GW_HI * 4u + o);
                ldsm_x4(bl0, bl1, bl2, bl3, base + GW_LO * 4u + o);
#pragma unroll
                for (int mt = 0; mt < 2; mt++) {
                    mma_bf16(acc[mt][2 * ntp],     ah[mt][0], ah[mt][1], ah[mt][2], ah[mt][3], bh0, bh1);
                    mma_bf16(acc[mt][2 * ntp],     ah[mt][0], ah[mt][1], ah[mt][2], ah[mt][3], bl0, bl1);
                    mma_bf16(acc[mt][2 * ntp],     al[mt][0], al[mt][1], al[mt][2], al[mt][3], bh0, bh1);
                    mma_bf16(acc[mt][2 * ntp + 1], ah[mt][0], ah[mt][1], ah[mt][2], ah[mt][3], bh2, bh3);
                    mma_bf16(acc[mt][2 * ntp + 1], ah[mt][0], ah[mt][1], ah[mt][2], ah[mt][3], bl2, bl3);
                    mma_bf16(acc[mt][2 * ntp + 1], al[mt][0], al[mt][1], al[mt][2], al[mt][3], bh2, bh3);
                }
            }
        }
    }

    // epilogue
#pragma unroll
    for (int mt = 0; mt < 2; mt++) {
#pragma unroll
        for (int nt = 0; nt < 8; nt++) {
            int gm0 = m_base + wm * 32 + mt * 16 + r;
            int gm1 = gm0 + 8;
            int gn  = n_base + wn * 64 + nt * 8 + c * 2;
            float b0v = bias[gn], b1v = bias[gn + 1];
            float f00 = acc[mt][nt].x + b0v, f01 = acc[mt][nt].y + b1v;
            float f10 = acc[mt][nt].z + b0v, f11 = acc[mt][nt].w + b1v;
            if (mode == 1) { f00 *= QSCALE; f01 *= QSCALE; f10 *= QSCALE; f11 *= QSCALE; }

            if (mode == 0) {
                *(float2*)(Cf + (size_t)gm0 * D_ + gn) = make_float2(f00, f01);
                *(float2*)(Cf + (size_t)gm1 * D_ + gn) = make_float2(f10, f11);
            } else if (mode == 1 || mode == 2) {
                uint32_t h0, l0, h1, l1;
                split2(f00, f01, h0, l0);
                split2(f10, f11, h1, l1);
                Ch[(size_t)gm0 * 512 + gn / 2] = h0;
                Cl[(size_t)gm0 * 512 + gn / 2] = l0;
                Ch[(size_t)gm1 * 512 + gn / 2] = h1;
                Cl[(size_t)gm1 * 512 + gn / 2] = l1;
            } else {
                __nv_bfloat16* Chb = (__nv_bfloat16*)Ch;
                __nv_bfloat16* Clb = (__nv_bfloat16*)Cl;
                float fv[2][2] = {{f00, f01}, {f10, f11}};
                int gms[2] = {gm0, gm1};
#pragma unroll
                for (int i = 0; i < 2; i++)
#pragma unroll
                    for (int j = 0; j < 2; j++) {
                        int m = gms[i], n = gn + j;
                        int bb = m >> 11, s = m & 2047;
                        int hh = n >> 6, dh = n & 63;
                        size_t idx = (((size_t)(bb * H_ + hh) * DH_ + dh) * S_) + s;
                        __nv_bfloat16 hv = __float2bfloat16_rn(fv[i][j]);
                        float lvf = fv[i][j] - __bfloat162float(hv);
                        Chb[idx] = hv;
                        Clb[idx] = __float2bfloat16_rn(lvf);
                    }
            }
        }
    }
}

__global__ __launch_bounds__(256, 2) void gemm_qkv(
    const float* __restrict__ b_q, const float* __restrict__ b_k,
    const float* __restrict__ b_v)
{
    extern __shared__ uint32_t sg[];
    const uint32_t sb = (uint32_t)__cvta_generic_to_shared(sg);
    const int z = blockIdx.z;
    if (z == 0)
        gemm_core(g_Xqh, g_Xql, g_Wqh, g_Wql, b_q, nullptr, g_Qh, g_Ql, 1, sb);
    else if (z == 1)
        gemm_core(g_Xkh, g_Xkl, g_Wkh, g_Wkl, b_k, nullptr, g_Kh, g_Kl, 2, sb);
    else
        gemm_core(g_Xvh, g_Xvl, g_Wvh, g_Wvl, b_v, nullptr, g_Vh, g_Vl, 3, sb);
}

__global__ __launch_bounds__(256, 2) void gemm_out(
    const float* __restrict__ b_o, float* __restrict__ out)
{
    extern __shared__ uint32_t sg[];
    const uint32_t sb = (uint32_t)__cvta_generic_to_shared(sg);
    gemm_core(g_AOh, g_AOl, g_Woh, g_Wol, b_o, out, nullptr, nullptr, 0, sb);
}

// ---------------------------------------------------------------------------
// Flash attention, mma bf16x3, exp2 softmax. 2-stage cp.async pipeline,
// ONE __syncthreads per key-block. 4 warps, 32 q-rows/warp.
// Dyn smem: 2 x 4 planes x 64 x 36 u32 = 73728 B (2 CTAs/SM).
// ---------------------------------------------------------------------------
__global__ __launch_bounds__(128, 2) void attn_mma(
    const uint32_t* __restrict__ Qh, const uint32_t* __restrict__ Ql,
    const uint32_t* __restrict__ Kh, const uint32_t* __restrict__ Kl,
    const uint32_t* __restrict__ Vh, const uint32_t* __restrict__ Vl,
    uint32_t* __restrict__ AOh, uint32_t* __restrict__ AOl)
{
    extern __shared__ uint32_t smu[];
    const int tid  = threadIdx.x;
    const int lane = tid & 31;
    const int wid  = tid >> 5;
    const int r    = lane >> 2;
    const int c    = lane & 3;
    const int h    = blockIdx.y;
    const int b    = blockIdx.z;
    const int q0   = blockIdx.x * 128 + wid * 32;

    const size_t qk_base = ((size_t)b * S_ * D_ + h * DH_) / 2;
    const size_t v_base  = ((size_t)(b * H_ + h) * DH_ * S_) / 2;
    const uint32_t* Qh32 = Qh + qk_base;
    const uint32_t* Ql32 = Ql + qk_base;
    const uint32_t* Kh32 = Kh + qk_base;
    const uint32_t* Kl32 = Kl + qk_base;
    const uint32_t* Vh32 = Vh + v_base;
    const uint32_t* Vl32 = Vl + v_base;

    const uint32_t sbase = (uint32_t)__cvta_generic_to_shared(smu);
    const int lr  = (lane & 7) + ((lane >> 4) << 3);
    const int lc4 = ((lane >> 3) & 1) * 4;
    const uint32_t laddr = (uint32_t)(lr * 36 + lc4) * 4;

    uint32_t qh[2][4][4], ql[2][4][4];
#pragma unroll
    for (int mt = 0; mt < 2; mt++) {
        int rb = q0 + mt * 16;
#pragma unroll
        for (int kt = 0; kt < 4; kt++) {
            qh[mt][kt][0] = Qh32[(size_t)(rb + r) * 512 + kt * 8 + c];
            qh[mt][kt][1] = Qh32[(size_t)(rb + 8 + r) * 512 + kt * 8 + c];
            qh[mt][kt][2] = Qh32[(size_t)(rb + r) * 512 + kt * 8 + c + 4];
            qh[mt][kt][3] = Qh32[(size_t)(rb + 8 + r) * 512 + kt * 8 + c + 4];
            ql[mt][kt][0] = Ql32[(size_t)(rb + r) * 512 + kt * 8 + c];
            ql[mt][kt][1] = Ql32[(size_t)(rb + 8 + r) * 512 + kt * 8 + c];
            ql[mt][kt][2] = Ql32[(size_t)(rb + r) * 512 + kt * 8 + c + 4];
            ql[mt][kt][3] = Ql32[(size_t)(rb + 8 + r) * 512 + kt * 8 + c + 4];
        }
    }

    float4 oacc[2][8];
#pragma unroll
    for (int mt = 0; mt < 2; mt++)
#pragma unroll
        for (int j = 0; j < 8; j++) oacc[mt][j] = make_float4(0.f, 0.f, 0.f, 0.f);
    float mi[2][2], li[2][2];
#pragma unroll
    for (int mt = 0; mt < 2; mt++) { mi[mt][0] = mi[mt][1] = -1e30f; li[mt][0] = li[mt][1] = 0.f; }

    auto prefetch = [&](int kb) {
        uint32_t bufb = sbase + (uint32_t)(kb & 1) * 9216 * 4;
#pragma unroll
        for (int t = 0; t < 4; t++) {
            int i = tid + t * 128;
            int row = i >> 3, col = (i & 7) * 4;
            uint32_t off = (uint32_t)(row * 36 + col) * 4;
            size_t kg = (size_t)(kb * 64 + row) * 512 + col;
            size_t vg = (size_t)row * 1024 + kb * 32 + col;
            cp16(bufb + off,            Kh32 + kg);
            cp16(bufb + 2304 * 4 + off, Kl32 + kg);
            cp16(bufb + 4608 * 4 + off, Vh32 + vg);
            cp16(bufb + 6912 * 4 + off, Vl32 + vg);
        }
        cp_commit();
    };

    prefetch(0);

    for (int kb = 0; kb < NKB; kb++) {
        asm volatile("cp.async.wait_group 0;" ::: "memory");
        __syncthreads();
        if (kb + 1 < NKB) prefetch(kb + 1);

        uint32_t bufb = sbase + (uint32_t)(kb & 1) * 9216 * 4;
        uint32_t kh_b = bufb, kl_b = bufb + 2304 * 4;
        uint32_t vh_b = bufb + 4608 * 4, vl_b = bufb + 6912 * 4;

        float4 sacc[2][8];
#pragma unroll
        for (int mt = 0; mt < 2; mt++)
#pragma unroll
            for (int nt = 0; nt < 8; nt++) sacc[mt][nt] = make_float4(0.f, 0.f, 0.f, 0.f);
#pragma unroll
        for (int ng = 0; ng < 4; ng++) {
#pragma unroll
            for (int kt = 0; kt < 4; kt++) {
                uint32_t o = laddr + (uint32_t)(ng * 576 + kt * 8) * 4;
                uint32_t h0, h1, h2, h3, l0, l1, l2, l3;
                ldsm_x4(h0, h1, h2, h3, kh_b + o);
                ldsm_x4(l0, l1, l2, l3, kl_b + o);
#pragma unroll
                for (int mt = 0; mt < 2; mt++) {
                    mma_bf16(sacc[mt][2 * ng],     qh[mt][kt][0], qh[mt][kt][1], qh[mt][kt][2], qh[mt][kt][3], h0, h1);
                    mma_bf16(sacc[mt][2 * ng],     qh[mt][kt][0], qh[mt][kt][1], qh[mt][kt][2], qh[mt][kt][3], l0, l1);
                    mma_bf16(sacc[mt][2 * ng],     ql[mt][kt][0], ql[mt][kt][1], ql[mt][kt][2], ql[mt][kt][3], h0, h1);
                    mma_bf16(sacc[mt][2 * ng + 1], qh[mt][kt][0], qh[mt][kt][1], qh[mt][kt][2], qh[mt][kt][3], h2, h3);
                    mma_bf16(sacc[mt][2 * ng + 1], qh[mt][kt][0], qh[mt][kt][1], qh[mt][kt][2], qh[mt][kt][3], l2, l3);
                    mma_bf16(sacc[mt][2 * ng + 1], ql[mt][kt][0], ql[mt][kt][1], ql[mt][kt][2], ql[mt][kt][3], h2, h3);
                }
            }
        }

        uint32_t ph[2][4][4], pl[2][4][4];
#pragma unroll
        for (int mt = 0; mt < 2; mt++) {
            float m0 = -1e30f, m1 = -1e30f;
#pragma unroll
            for (int nt = 0; nt < 8; nt++) {
                m0 = fmaxf(m0, fmaxf(sacc[mt][nt].x, sacc[mt][nt].y));
                m1 = fmaxf(m1, fmaxf(sacc[mt][nt].z, sacc[mt][nt].w));
            }
#pragma unroll
            for (int o = 1; o <= 2; o <<= 1) {
                m0 = fmaxf(m0, __shfl_xor_sync(0xffffffffu, m0, o));
                m1 = fmaxf(m1, __shfl_xor_sync(0xffffffffu, m1, o));
            }
            float mn0 = fmaxf(mi[mt][0], m0), mn1 = fmaxf(mi[mt][1], m1);
            float corr0 = exp2f(mi[mt][0] - mn0), corr1 = exp2f(mi[mt][1] - mn1);
            float rs0 = 0.f, rs1 = 0.f;
#pragma unroll
            for (int nt = 0; nt < 8; nt++) {
                sacc[mt][nt].x = exp2f(sacc[mt][nt].x - mn0);
                sacc[mt][nt].y = exp2f(sacc[mt][nt].y - mn0);
                sacc[mt][nt].z = exp2f(sacc[mt][nt].z - mn1);
                sacc[mt][nt].w = exp2f(sacc[mt][nt].w - mn1);
                rs0 += sacc[mt][nt].x + sacc[mt][nt].y;
                rs1 += sacc[mt][nt].z + sacc[mt][nt].w;
            }
#pragma unroll
            for (int o = 1; o <= 2; o <<= 1) {
                rs0 += __shfl_xor_sync(0xffffffffu, rs0, o);
                rs1 += __shfl_xor_sync(0xffffffffu, rs1, o);
            }
            li[mt][0] = li[mt][0] * corr0 + rs0;
            li[mt][1] = li[mt][1] * corr1 + rs1;
            mi[mt][0] = mn0; mi[mt][1] = mn1;
#pragma unroll
            for (int j = 0; j < 8; j++) {
                oacc[mt][j].x *= corr0; oacc[mt][j].y *= corr0;
                oacc[mt][j].z *= corr1; oacc[mt][j].w *= corr1;
            }
#pragma unroll
            for (int t = 0; t < 4; t++) {
                split2(sacc[mt][2 * t].x,     sacc[mt][2 * t].y,     ph[mt][t][0], pl[mt][t][0]);
                split2(sacc[mt][2 * t].z,     sacc[mt][2 * t].w,     ph[mt][t][1], pl[mt][t][1]);
                split2(sacc[mt][2 * t + 1].x, sacc[mt][2 * t + 1].y, ph[mt][t][2], pl[mt][t][2]);
                split2(sacc[mt][2 * t + 1].z, sacc[mt][2 * t + 1].w, ph[mt][t][3], pl[mt][t][3]);
            }
        }

#pragma unroll
        for (int jg = 0; jg < 4; jg++) {
#pragma unroll
            for (int kt = 0; kt < 4; kt++) {
                uint32_t o = laddr + (uint32_t)(jg * 576 + kt * 8) * 4;
                uint32_t h0, h1, h2, h3, l0, l1, l2, l3;
                ldsm_x4(h0, h1, h2, h3, vh_b + o);
                ldsm_x4(l0, l1, l2, l3, vl_b + o);
#pragma unroll
                for (int mt = 0; mt < 2; mt++) {
                    mma_bf16(oacc[mt][2 * jg],     ph[mt][kt][0], ph[mt][kt][1], ph[mt][kt][2], ph[mt][kt][3], h0, h1);
                    mma_bf16(oacc[mt][2 * jg],     ph[mt][kt][0], ph[mt][kt][1], ph[mt][kt][2], ph[mt][kt][3], l0, l1);
                    mma_bf16(oacc[mt][2 * jg],     pl[mt][kt][0], pl[mt][kt][1], pl[mt][kt][2], pl[mt][kt][3], h0, h1);
                    mma_bf16(oacc[mt][2 * jg + 1], ph[mt][kt][0], ph[mt][kt][1], ph[mt][kt][2], ph[mt][kt][3], h2, h3);
                    mma_bf16(oacc[mt][2 * jg + 1], ph[mt][kt][0], ph[mt][kt][1], ph[mt][kt][2], ph[mt][kt][3], l2, l3);
                    mma_bf16(oacc[mt][2 * jg + 1], pl[mt][kt][0], pl[mt][kt][1], pl[mt][kt][2], pl[mt][kt][3], h2, h3);
                }
            }
        }
    }

#pragma unroll
    for (int mt = 0; mt < 2; mt++) {
        float inv0 = 1.f / li[mt][0], inv1 = 1.f / li[mt][1];
        const size_t row0 = ((size_t)b * S_ + q0 + mt * 16 + r) * 512;
        const size_t row1 = row0 + 8 * 512;
#pragma unroll
        for (int j = 0; j < 8; j++) {
            int w = h * 32 + j * 4 + c;
            uint32_t hw, lw;
            split2(oacc[mt][j].x * inv0, oacc[mt][j].y * inv0, hw, lw);
            AOh[row0 + w] = hw; AOl[row0 + w] = lw;
            split2(oacc[mt][j].z * inv1, oacc[mt][j].w * inv1, hw, lw);
            AOh[row1 + w] = hw; AOl[row1 + w] = lw;
        }
    }
}

// ---------------------------------------------------------------------------
extern "C" void kernel_launch(void* const* d_in, const int* in_sizes, int n_in,
                              void* d_out, int out_size)
{
    const float* queries = (const float*)d_in[0];
    const float* keys    = (const float*)d_in[1];
    const float* values  = (const float*)d_in[2];
    const float* W_q = (const float*)d_in[3];
    const float* b_q = (const float*)d_in[4];
    const float* W_k = (const float*)d_in[5];
    const float* b_k = (const float*)d_in[6];
    const float* W_v = (const float*)d_in[7];
    const float* b_v = (const float*)d_in[8];
    const float* W_o = (const float*)d_in[9];
    const float* b_o = (const float*)d_in[10];
    float* out = (float*)d_out;

    uint32_t *Qh, *Ql, *Kh, *Kl, *Vh, *Vl, *AOh, *AOl;
    cudaGetSymbolAddress((void**)&Qh, g_Qh);
    cudaGetSymbolAddress((void**)&Ql, g_Ql);
    cudaGetSymbolAddress((void**)&Kh, g_Kh);
    cudaGetSymbolAddress((void**)&Kl, g_Kl);
    cudaGetSymbolAddress((void**)&Vh, g_Vh);
    cudaGetSymbolAddress((void**)&Vl, g_Vl);
    cudaGetSymbolAddress((void**)&AOh, g_AOh);
    cudaGetSymbolAddress((void**)&AOl, g_AOl);

    const int gsmem = 2 * GSTG * 4;   // 81920
    cudaFuncSetAttribute(gemm_qkv, cudaFuncAttributeMaxDynamicSharedMemorySize, gsmem);
    cudaFuncSetAttribute(gemm_out, cudaFuncAttributeMaxDynamicSharedMemorySize, gsmem);
    const int asmem = 2 * 9216 * 4;   // 73728
    cudaFuncSetAttribute(attn_mma, cudaFuncAttributeMaxDynamicSharedMemorySize, asmem);

    split_all<<<16384, 256>>>(queries, keys, values, W_q, W_k, W_v, W_o);

    dim3 qkv_grid(D_ / 128, (B_ * S_) / 128, 3);
    gemm_qkv<<<qkv_grid, 256, gsmem>>>(b_q, b_k, b_v);

    dim3 agrid(S_ / 128, H_, B_);
    attn_mma<<<agrid, 128, asmem>>>(Qh, Ql, Kh, Kl, Vh, Vl, AOh, AOl);

    dim3 ogrid(D_ / 128, (B_ * S_) / 128);
    gemm_out<<<ogrid, 256, gsmem>>>(b_o, out);
}

// round 10
// speedup vs baseline: 1.1006x; 1.0038x over previous
#include <cuda_runtime.h>
#include <cuda_bf16.h>
#include <stdint.h>

#define B_  2
#define S_  2048
#define D_  1024
#define H_  16
#define DH_ 64
#define NE_ (B_ * S_ * D_)
#define NKB (S_ / 64)
#define NW_ (D_ * D_)

// Scratch (allocation-free): bf16 hi/lo planes packed 2-per-u32.
__device__ uint32_t g_Qh[NE_ / 2], g_Ql[NE_ / 2];   // proj Q, pre-scaled
__device__ uint32_t g_Kh[NE_ / 2], g_Kl[NE_ / 2];   // proj K
__device__ uint32_t g_Vh[NE_ / 2], g_Vl[NE_ / 2];   // proj V transposed [b][h][dh][s]
__device__ uint32_t g_AOh[NE_ / 2], g_AOl[NE_ / 2]; // attention output planes
__device__ uint32_t g_Xqh[NE_ / 2], g_Xql[NE_ / 2];
__device__ uint32_t g_Xkh[NE_ / 2], g_Xkl[NE_ / 2];
__device__ uint32_t g_Xvh[NE_ / 2], g_Xvl[NE_ / 2];
__device__ uint32_t g_Wqh[NW_ / 2], g_Wql[NW_ / 2];
__device__ uint32_t g_Wkh[NW_ / 2], g_Wkl[NW_ / 2];
__device__ uint32_t g_Wvh[NW_ / 2], g_Wvl[NW_ / 2];
__device__ uint32_t g_Woh[NW_ / 2], g_Wol[NW_ / 2];

// (1/8) * log2(e): folds softmax exp -> exp2
#define QSCALE 0.1803368801111204f

// ---------------------------------------------------------------------------
__device__ __forceinline__ void split2(float x, float y, uint32_t& hi, uint32_t& lo)
{
    __nv_bfloat162 h = __floats2bfloat162_rn(x, y);
    float rx = x - __bfloat162float(h.x);
    float ry = y - __bfloat162float(h.y);
    __nv_bfloat162 l = __floats2bfloat162_rn(rx, ry);
    hi = *reinterpret_cast<uint32_t*>(&h);
    lo = *reinterpret_cast<uint32_t*>(&l);
}

__device__ __forceinline__ void mma_bf16(float4& d,
    uint32_t a0, uint32_t a1, uint32_t a2, uint32_t a3,
    uint32_t b0, uint32_t b1)
{
    asm volatile(
        "mma.sync.aligned.m16n8k16.row.col.f32.bf16.bf16.f32 "
        "{%0,%1,%2,%3},{%4,%5,%6,%7},{%8,%9},{%0,%1,%2,%3};"
        : "+f"(d.x), "+f"(d.y), "+f"(d.z), "+f"(d.w)
        : "r"(a0), "r"(a1), "r"(a2), "r"(a3), "r"(b0), "r"(b1));
}

__device__ __forceinline__ void ldsm_x4(uint32_t& r0, uint32_t& r1,
                                        uint32_t& r2, uint32_t& r3, uint32_t addr)
{
    asm volatile("ldmatrix.sync.aligned.m8n8.x4.shared.b16 {%0,%1,%2,%3}, [%4];"
                 : "=r"(r0), "=r"(r1), "=r"(r2), "=r"(r3) : "r"(addr));
}

__device__ __forceinline__ void cp16(uint32_t smaddr, const void* g)
{
    asm volatile("cp.async.cg.shared.global [%0], [%1], 16;" :: "r"(smaddr), "l"(g));
}
__device__ __forceinline__ void cp_commit()
{
    asm volatile("cp.async.commit_group;" ::: "memory");
}

// ---------------------------------------------------------------------------
// ONE fused split pass.
// ---------------------------------------------------------------------------
__global__ __launch_bounds__(256) void split_all(
    const float* __restrict__ q, const float* __restrict__ k, const float* __restrict__ v,
    const float* __restrict__ wq, const float* __restrict__ wk,
    const float* __restrict__ wv, const float* __restrict__ wo)
{
    const int bid = blockIdx.x;
    const float* src;
    uint32_t *hi, *lo;
    int i;
    if (bid < 12288) {
        int seg = bid >> 12;
        i = (bid & 4095) * 256 + threadIdx.x;
        if (seg == 0)      { src = q; hi = g_Xqh; lo = g_Xql; }
        else if (seg == 1) { src = k; hi = g_Xkh; lo = g_Xkl; }
        else               { src = v; hi = g_Xvh; lo = g_Xvl; }
    } else {
        int seg = (bid - 12288) >> 10;
        i = ((bid - 12288) & 1023) * 256 + threadIdx.x;
        if (seg == 0)      { src = wq; hi = g_Wqh; lo = g_Wql; }
        else if (seg == 1) { src = wk; hi = g_Wkh; lo = g_Wkl; }
        else if (seg == 2) { src = wv; hi = g_Wvh; lo = g_Wvl; }
        else               { src = wo; hi = g_Woh; lo = g_Wol; }
    }
    float4 val = ((const float4*)src)[i];
    uint32_t h0, l0, h1, l1;
    split2(val.x, val.y, h0, l0);
    split2(val.z, val.w, h1, l1);
    ((uint2*)hi)[i] = make_uint2(h0, h1);
    ((uint2*)lo)[i] = make_uint2(l0, l1);
}

// ---------------------------------------------------------------------------
// bf16x3 GEMM core: BM=128, BN=128, BK=32, 2 stages, one sync/iter,
// TERM-MAJOR mma ordering (same-acc reuse distance 16).
// ---------------------------------------------------------------------------
#define GSTG   10240u
#define GA_LO  2560u
#define GW_HI  5120u
#define GW_LO  7680u

__device__ __forceinline__ void gemm_core(
    const uint32_t* __restrict__ Ah, const uint32_t* __restrict__ Al,
    const uint32_t* __restrict__ Wh, const uint32_t* __restrict__ Wl,
    const float* __restrict__ bias,
    float* __restrict__ Cf, uint32_t* __restrict__ Ch, uint32_t* __restrict__ Cl,
    int mode, uint32_t sb)
{
    const int tid  = threadIdx.x;
    const int lane = tid & 31;
    const int wid  = tid >> 5;
    const int wm   = wid & 3;
    const int wn   = wid >> 2;
    const int r    = lane >> 2;
    const int c    = lane & 3;

    const int m_base = blockIdx.y * 128;
    const int n_base = blockIdx.x * 128;
    const int KW = D_ >> 1;

    const int lrA = (lane & 7) + (((lane >> 3) & 1) << 3);
    const int lcA = (lane >> 4) * 4;
    const int lrB = (lane & 7) + ((lane >> 4) << 3);
    const int lcB = ((lane >> 3) & 1) * 4;

    auto prefetch = [&](int ktile) {
        uint32_t base = sb + (uint32_t)(ktile & 1) * GSTG * 4u;
        int ktw = ktile * 16;
#pragma unroll
        for (int t = 0; t < 2; t++) {
            int idx = tid + t * 256;
            int row = idx >> 2, cg = (idx & 3) * 4;
            uint32_t so = (uint32_t)(row * 20 + cg) * 4u;
            size_t ga = (size_t)(m_base + row) * KW + ktw + cg;
            size_t gw = (size_t)(n_base + row) * KW + ktw + cg;
            cp16(base + so,                Ah + ga);
            cp16(base + GA_LO * 4u + so,   Al + ga);
            cp16(base + GW_HI * 4u + so,   Wh + gw);
            cp16(base + GW_LO * 4u + so,   Wl + gw);
        }
        cp_commit();
    };

    float4 acc[2][8];
#pragma unroll
    for (int i = 0; i < 2; i++)
#pragma unroll
        for (int j = 0; j < 8; j++) acc[i][j] = make_float4(0.f, 0.f, 0.f, 0.f);

    const int NT = D_ / 32;
    prefetch(0);

    for (int kt = 0; kt < NT; kt++) {
        asm volatile("cp.async.wait_group 0;" ::: "memory");
        __syncthreads();
        if (kt + 1 < NT) prefetch(kt + 1);

        uint32_t base = sb + (uint32_t)(kt & 1) * GSTG * 4u;

#pragma unroll
        for (int ks = 0; ks < 2; ks++) {
            // hoist ALL fragments for this k16
            uint32_t ah[2][4], al[2][4];
#pragma unroll
            for (int mt = 0; mt < 2; mt++) {
                uint32_t o = (uint32_t)((wm * 32 + mt * 16 + lrA) * 20 + ks * 8 + lcA) * 4u;
                ldsm_x4(ah[mt][0], ah[mt][1], ah[mt][2], ah[mt][3], base + o);
                ldsm_x4(al[mt][0], al[mt][1], al[mt][2], al[mt][3], base + GA_LO * 4u + o);
            }
            uint32_t bh[4][4], bl[4][4];
#pragma unroll
            for (int ntp = 0; ntp < 4; ntp++) {
                uint32_t o = (uint32_t)((wn * 64 + ntp * 16 + lrB) * 20 + ks * 8 + lcB) * 4u;
                ldsm_x4(bh[ntp][0], bh[ntp][1], bh[ntp][2], bh[ntp][3], base + GW_HI * 4u + o);
                ldsm_x4(bl[ntp][0], bl[ntp][1], bl[ntp][2], bl[ntp][3], base + GW_LO * 4u + o);
            }
            // term hh: 16 independent accumulators
#pragma unroll
            for (int ntp = 0; ntp < 4; ntp++)
#pragma unroll
                for (int mt = 0; mt < 2; mt++) {
                    mma_bf16(acc[mt][2 * ntp],     ah[mt][0], ah[mt][1], ah[mt][2], ah[mt][3], bh[ntp][0], bh[ntp][1]);
                    mma_bf16(acc[mt][2 * ntp + 1], ah[mt][0], ah[mt][1], ah[mt][2], ah[mt][3], bh[ntp][2], bh[ntp][3]);
                }
            // term hl
#pragma unroll
            for (int ntp = 0; ntp < 4; ntp++)
#pragma unroll
                for (int mt = 0; mt < 2; mt++) {
                    mma_bf16(acc[mt][2 * ntp],     ah[mt][0], ah[mt][1], ah[mt][2], ah[mt][3], bl[ntp][0], bl[ntp][1]);
                    mma_bf16(acc[mt][2 * ntp + 1], ah[mt][0], ah[mt][1], ah[mt][2], ah[mt][3], bl[ntp][2], bl[ntp][3]);
                }
            // term lh
#pragma unroll
            for (int ntp = 0; ntp < 4; ntp++)
#pragma unroll
                for (int mt = 0; mt < 2; mt++) {
                    mma_bf16(acc[mt][2 * ntp],     al[mt][0], al[mt][1], al[mt][2], al[mt][3], bh[ntp][0], bh[ntp][1]);
                    mma_bf16(acc[mt][2 * ntp + 1], al[mt][0], al[mt][1], al[mt][2], al[mt][3], bh[ntp][2], bh[ntp][3]);
                }
        }
    }

    // epilogue
#pragma unroll
    for (int mt = 0; mt < 2; mt++) {
#pragma unroll
        for (int nt = 0; nt < 8; nt++) {
            int gm0 = m_base + wm * 32 + mt * 16 + r;
            int gm1 = gm0 + 8;
            int gn  = n_base + wn * 64 + nt * 8 + c * 2;
            float b0v = bias[gn], b1v = bias[gn + 1];
            float f00 = acc[mt][nt].x + b0v, f01 = acc[mt][nt].y + b1v;
            float f10 = acc[mt][nt].z + b0v, f11 = acc[mt][nt].w + b1v;
            if (mode == 1) { f00 *= QSCALE; f01 *= QSCALE; f10 *= QSCALE; f11 *= QSCALE; }

            if (mode == 0) {
                *(float2*)(Cf + (size_t)gm0 * D_ + gn) = make_float2(f00, f01);
                *(float2*)(Cf + (size_t)gm1 * D_ + gn) = make_float2(f10, f11);
            } else if (mode == 1 || mode == 2) {
                uint32_t h0, l0, h1, l1;
                split2(f00, f01, h0, l0);
                split2(f10, f11, h1, l1);
                Ch[(size_t)gm0 * 512 + gn / 2] = h0;
                Cl[(size_t)gm0 * 512 + gn / 2] = l0;
                Ch[(size_t)gm1 * 512 + gn / 2] = h1;
                Cl[(size_t)gm1 * 512 + gn / 2] = l1;
            } else {
                __nv_bfloat16* Chb = (__nv_bfloat16*)Ch;
                __nv_bfloat16* Clb = (__nv_bfloat16*)Cl;
                float fv[2][2] = {{f00, f01}, {f10, f11}};
                int gms[2] = {gm0, gm1};
#pragma unroll
                for (int i = 0; i < 2; i++)
#pragma unroll
                    for (int j = 0; j < 2; j++) {
                        int m = gms[i], n = gn + j;
                        int bb = m >> 11, s = m & 2047;
                        int hh = n >> 6, dh = n & 63;
                        size_t idx = (((size_t)(bb * H_ + hh) * DH_ + dh) * S_) + s;
                        __nv_bfloat16 hv = __float2bfloat16_rn(fv[i][j]);
                        float lvf = fv[i][j] - __bfloat162float(hv);
                        Chb[idx] = hv;
                        Clb[idx] = __float2bfloat16_rn(lvf);
                    }
            }
        }
    }
}

__global__ __launch_bounds__(256, 2) void gemm_qkv(
    const float* __restrict__ b_q, const float* __restrict__ b_k,
    const float* __restrict__ b_v)
{
    extern __shared__ uint32_t sg[];
    const uint32_t sb = (uint32_t)__cvta_generic_to_shared(sg);
    const int z = blockIdx.z;
    if (z == 0)
        gemm_core(g_Xqh, g_Xql, g_Wqh, g_Wql, b_q, nullptr, g_Qh, g_Ql, 1, sb);
    else if (z == 1)
        gemm_core(g_Xkh, g_Xkl, g_Wkh, g_Wkl, b_k, nullptr, g_Kh, g_Kl, 2, sb);
    else
        gemm_core(g_Xvh, g_Xvl, g_Wvh, g_Wvl, b_v, nullptr, g_Vh, g_Vl, 3, sb);
}

__global__ __launch_bounds__(256, 2) void gemm_out(
    const float* __restrict__ b_o, float* __restrict__ out)
{
    extern __shared__ uint32_t sg[];
    const uint32_t sb = (uint32_t)__cvta_generic_to_shared(sg);
    gemm_core(g_AOh, g_AOl, g_Woh, g_Wol, b_o, out, nullptr, nullptr, 0, sb);
}

// ---------------------------------------------------------------------------
// Flash attention, mma bf16x3, exp2 softmax. 2-stage cp.async, one sync/block,
// term-major MMA ordering inside each (ng,kt) block (same-acc distance 4).
// ---------------------------------------------------------------------------
__global__ __launch_bounds__(128, 2) void attn_mma(
    const uint32_t* __restrict__ Qh, const uint32_t* __restrict__ Ql,
    const uint32_t* __restrict__ Kh, const uint32_t* __restrict__ Kl,
    const uint32_t* __restrict__ Vh, const uint32_t* __restrict__ Vl,
    uint32_t* __restrict__ AOh, uint32_t* __restrict__ AOl)
{
    extern __shared__ uint32_t smu[];
    const int tid  = threadIdx.x;
    const int lane = tid & 31;
    const int wid  = tid >> 5;
    const int r    = lane >> 2;
    const int c    = lane & 3;
    const int h    = blockIdx.y;
    const int b    = blockIdx.z;
    const int q0   = blockIdx.x * 128 + wid * 32;

    const size_t qk_base = ((size_t)b * S_ * D_ + h * DH_) / 2;
    const size_t v_base  = ((size_t)(b * H_ + h) * DH_ * S_) / 2;
    const uint32_t* Qh32 = Qh + qk_base;
    const uint32_t* Ql32 = Ql + qk_base;
    const uint32_t* Kh32 = Kh + qk_base;
    const uint32_t* Kl32 = Kl + qk_base;
    const uint32_t* Vh32 = Vh + v_base;
    const uint32_t* Vl32 = Vl + v_base;

    const uint32_t sbase = (uint32_t)__cvta_generic_to_shared(smu);
    const int lr  = (lane & 7) + ((lane >> 4) << 3);
    const int lc4 = ((lane >> 3) & 1) * 4;
    const uint32_t laddr = (uint32_t)(lr * 36 + lc4) * 4;

    uint32_t qh[2][4][4], ql[2][4][4];
#pragma unroll
    for (int mt = 0; mt < 2; mt++) {
        int rb = q0 + mt * 16;
#pragma unroll
        for (int kt = 0; kt < 4; kt++) {
            qh[mt][kt][0] = Qh32[(size_t)(rb + r) * 512 + kt * 8 + c];
            qh[mt][kt][1] = Qh32[(size_t)(rb + 8 + r) * 512 + kt * 8 + c];
            qh[mt][kt][2] = Qh32[(size_t)(rb + r) * 512 + kt * 8 + c + 4];
            qh[mt][kt][3] = Qh32[(size_t)(rb + 8 + r) * 512 + kt * 8 + c + 4];
            ql[mt][kt][0] = Ql32[(size_t)(rb + r) * 512 + kt * 8 + c];
            ql[mt][kt][1] = Ql32[(size_t)(rb + 8 + r) * 512 + kt * 8 + c];
            ql[mt][kt][2] = Ql32[(size_t)(rb + r) * 512 + kt * 8 + c + 4];
            ql[mt][kt][3] = Ql32[(size_t)(rb + 8 + r) * 512 + kt * 8 + c + 4];
        }
    }

    float4 oacc[2][8];
#pragma unroll
    for (int mt = 0; mt < 2; mt++)
#pragma unroll
        for (int j = 0; j < 8; j++) oacc[mt][j] = make_float4(0.f, 0.f, 0.f, 0.f);
    float mi[2][2], li[2][2];
#pragma unroll
    for (int mt = 0; mt < 2; mt++) { mi[mt][0] = mi[mt][1] = -1e30f; li[mt][0] = li[mt][1] = 0.f; }

    auto prefetch = [&](int kb) {
        uint32_t bufb = sbase + (uint32_t)(kb & 1) * 9216 * 4;
#pragma unroll
        for (int t = 0; t < 4; t++) {
            int i = tid + t * 128;
            int row = i >> 3, col = (i & 7) * 4;
            uint32_t off = (uint32_t)(row * 36 + col) * 4;
            size_t kg = (size_t)(kb * 64 + row) * 512 + col;
            size_t vg = (size_t)row * 1024 + kb * 32 + col;
            cp16(bufb + off,            Kh32 + kg);
            cp16(bufb + 2304 * 4 + off, Kl32 + kg);
            cp16(bufb + 4608 * 4 + off, Vh32 + vg);
            cp16(bufb + 6912 * 4 + off, Vl32 + vg);
        }
        cp_commit();
    };

    prefetch(0);

    for (int kb = 0; kb < NKB; kb++) {
        asm volatile("cp.async.wait_group 0;" ::: "memory");
        __syncthreads();
        if (kb + 1 < NKB) prefetch(kb + 1);

        uint32_t bufb = sbase + (uint32_t)(kb & 1) * 9216 * 4;
        uint32_t kh_b = bufb, kl_b = bufb + 2304 * 4;
        uint32_t vh_b = bufb + 4608 * 4, vl_b = bufb + 6912 * 4;

        float4 sacc[2][8];
#pragma unroll
        for (int mt = 0; mt < 2; mt++)
#pragma unroll
            for (int nt = 0; nt < 8; nt++) sacc[mt][nt] = make_float4(0.f, 0.f, 0.f, 0.f);
#pragma unroll
        for (int ng = 0; ng < 4; ng++) {
#pragma unroll
            for (int kt = 0; kt < 4; kt++) {
                uint32_t o = laddr + (uint32_t)(ng * 576 + kt * 8) * 4;
                uint32_t h0, h1, h2, h3, l0, l1, l2, l3;
                ldsm_x4(h0, h1, h2, h3, kh_b + o);
                ldsm_x4(l0, l1, l2, l3, kl_b + o);
                // term-major: distance 4 between same-acc writes
#pragma unroll
                for (int mt = 0; mt < 2; mt++) {
                    mma_bf16(sacc[mt][2 * ng],     qh[mt][kt][0], qh[mt][kt][1], qh[mt][kt][2], qh[mt][kt][3], h0, h1);
                    mma_bf16(sacc[mt][2 * ng + 1], qh[mt][kt][0], qh[mt][kt][1], qh[mt][kt][2], qh[mt][kt][3], h2, h3);
                }
#pragma unroll
                for (int mt = 0; mt < 2; mt++) {
                    mma_bf16(sacc[mt][2 * ng],     qh[mt][kt][0], qh[mt][kt][1], qh[mt][kt][2], qh[mt][kt][3], l0, l1);
                    mma_bf16(sacc[mt][2 * ng + 1], qh[mt][kt][0], qh[mt][kt][1], qh[mt][kt][2], qh[mt][kt][3], l2, l3);
                }
#pragma unroll
                for (int mt = 0; mt < 2; mt++) {
                    mma_bf16(sacc[mt][2 * ng],     ql[mt][kt][0], ql[mt][kt][1], ql[mt][kt][2], ql[mt][kt][3], h0, h1);
                    mma_bf16(sacc[mt][2 * ng + 1], ql[mt][kt][0], ql[mt][kt][1], ql[mt][kt][2], ql[mt][kt][3], h2, h3);
                }
            }
        }

        uint32_t ph[2][4][4], pl[2][4][4];
#pragma unroll
        for (int mt = 0; mt < 2; mt++) {
            float m0 = -1e30f, m1 = -1e30f;
#pragma unroll
            for (int nt = 0; nt < 8; nt++) {
                m0 = fmaxf(m0, fmaxf(sacc[mt][nt].x, sacc[mt][nt].y));
                m1 = fmaxf(m1, fmaxf(sacc[mt][nt].z, sacc[mt][nt].w));
            }
#pragma unroll
            for (int o = 1; o <= 2; o <<= 1) {
                m0 = fmaxf(m0, __shfl_xor_sync(0xffffffffu, m0, o));
                m1 = fmaxf(m1, __shfl_xor_sync(0xffffffffu, m1, o));
            }
            float mn0 = fmaxf(mi[mt][0], m0), mn1 = fmaxf(mi[mt][1], m1);
            float corr0 = exp2f(mi[mt][0] - mn0), corr1 = exp2f(mi[mt][1] - mn1);
            float rs0 = 0.f, rs1 = 0.f;
#pragma unroll
            for (int nt = 0; nt < 8; nt++) {
                sacc[mt][nt].x = exp2f(sacc[mt][nt].x - mn0);
                sacc[mt][nt].y = exp2f(sacc[mt][nt].y - mn0);
                sacc[mt][nt].z = exp2f(sacc[mt][nt].z - mn1);
                sacc[mt][nt].w = exp2f(sacc[mt][nt].w - mn1);
                rs0 += sacc[mt][nt].x + sacc[mt][nt].y;
                rs1 += sacc[mt][nt].z + sacc[mt][nt].w;
            }
#pragma unroll
            for (int o = 1; o <= 2; o <<= 1) {
                rs0 += __shfl_xor_sync(0xffffffffu, rs0, o);
                rs1 += __shfl_xor_sync(0xffffffffu, rs1, o);
            }
            li[mt][0] = li[mt][0] * corr0 + rs0;
            li[mt][1] = li[mt][1] * corr1 + rs1;
            mi[mt][0] = mn0; mi[mt][1] = mn1;
#pragma unroll
            for (int j = 0; j < 8; j++) {
                oacc[mt][j].x *= corr0; oacc[mt][j].y *= corr0;
                oacc[mt][j].z *= corr1; oacc[mt][j].w *= corr1;
            }
#pragma unroll
            for (int t = 0; t < 4; t++) {
                split2(sacc[mt][2 * t].x,     sacc[mt][2 * t].y,     ph[mt][t][0], pl[mt][t][0]);
                split2(sacc[mt][2 * t].z,     sacc[mt][2 * t].w,     ph[mt][t][1], pl[mt][t][1]);
                split2(sacc[mt][2 * t + 1].x, sacc[mt][2 * t + 1].y, ph[mt][t][2], pl[mt][t][2]);
                split2(sacc[mt][2 * t + 1].z, sacc[mt][2 * t + 1].w, ph[mt][t][3], pl[mt][t][3]);
            }
        }

#pragma unroll
        for (int jg = 0; jg < 4; jg++) {
#pragma unroll
            for (int kt = 0; kt < 4; kt++) {
                uint32_t o = laddr + (uint32_t)(jg * 576 + kt * 8) * 4;
                uint32_t h0, h1, h2, h3, l0, l1, l2, l3;
                ldsm_x4(h0, h1, h2, h3, vh_b + o);
                ldsm_x4(l0, l1, l2, l3, vl_b + o);
#pragma unroll
                for (int mt = 0; mt < 2; mt++) {
                    mma_bf16(oacc[mt][2 * jg],     ph[mt][kt][0], ph[mt][kt][1], ph[mt][kt][2], ph[mt][kt][3], h0, h1);
                    mma_bf16(oacc[mt][2 * jg + 1], ph[mt][kt][0], ph[mt][kt][1], ph[mt][kt][2], ph[mt][kt][3], h2, h3);
                }
#pragma unroll
                for (int mt = 0; mt < 2; mt++) {
                    mma_bf16(oacc[mt][2 * jg],     ph[mt][kt][0], ph[mt][kt][1], ph[mt][kt][2], ph[mt][kt][3], l0, l1);
                    mma_bf16(oacc[mt][2 * jg + 1], ph[mt][kt][0], ph[mt][kt][1], ph[mt][kt][2], ph[mt][kt][3], l2, l3);
                }
#pragma unroll
                for (int mt = 0; mt < 2; mt++) {
                    mma_bf16(oacc[mt][2 * jg],     pl[mt][kt][0], pl[mt][kt][1], pl[mt][kt][2], pl[mt][kt][3], h0, h1);
                    mma_bf16(oacc[mt][2 * jg + 1], pl[mt][kt][0], pl[mt][kt][1], pl[mt][kt][2], pl[mt][kt][3], h2, h3);
                }
            }
        }
    }

#pragma unroll
    for (int mt = 0; mt < 2; mt++) {
        float inv0 = 1.f / li[mt][0], inv1 = 1.f / li[mt][1];
        const size_t row0 = ((size_t)b * S_ + q0 + mt * 16 + r) * 512;
        const size_t row1 = row0 + 8 * 512;
#pragma unroll
        for (int j = 0; j < 8; j++) {
            int w = h * 32 + j * 4 + c;
            uint32_t hw, lw;
            split2(oacc[mt][j].x * inv0, oacc[mt][j].y * inv0, hw, lw);
            AOh[row0 + w] = hw; AOl[row0 + w] = lw;
            split2(oacc[mt][j].z * inv1, oacc[mt][j].w * inv1, hw, lw);
            AOh[row1 + w] = hw; AOl[row1 + w] = lw;
        }
    }
}

// ---------------------------------------------------------------------------
extern "C" void kernel_launch(void* const* d_in, const int* in_sizes, int n_in,
                              void* d_out, int out_size)
{
    const float* queries = (const float*)d_in[0];
    const float* keys    = (const float*)d_in[1];
    const float* values  = (const float*)d_in[2];
    const float* W_q = (const float*)d_in[3];
    const float* b_q = (const float*)d_in[4];
    const float* W_k = (const float*)d_in[5];
    const float* b_k = (const float*)d_in[6];
    const float* W_v = (const float*)d_in[7];
    const float* b_v = (const float*)d_in[8];
    const float* W_o = (const float*)d_in[9];
    const float* b_o = (const float*)d_in[10];
    float* out = (float*)d_out;

    uint32_t *Qh, *Ql, *Kh, *Kl, *Vh, *Vl, *AOh, *AOl;
    cudaGetSymbolAddress((void**)&Qh, g_Qh);
    cudaGetSymbolAddress((void**)&Ql, g_Ql);
    cudaGetSymbolAddress((void**)&Kh, g_Kh);
    cudaGetSymbolAddress((void**)&Kl, g_Kl);
    cudaGetSymbolAddress((void**)&Vh, g_Vh);
    cudaGetSymbolAddress((void**)&Vl, g_Vl);
    cudaGetSymbolAddress((void**)&AOh, g_AOh);
    cudaGetSymbolAddress((void**)&AOl, g_AOl);

    const int gsmem = 2 * GSTG * 4;   // 81920
    cudaFuncSetAttribute(gemm_qkv, cudaFuncAttributeMaxDynamicSharedMemorySize, gsmem);
    cudaFuncSetAttribute(gemm_out, cudaFuncAttributeMaxDynamicSharedMemorySize, gsmem);
    const int asmem = 2 * 9216 * 4;   // 73728
    cudaFuncSetAttribute(attn_mma, cudaFuncAttributeMaxDynamicSharedMemorySize, asmem);

    split_all<<<16384, 256>>>(queries, keys, values, W_q, W_k, W_v, W_o);

    dim3 qkv_grid(D_ / 128, (B_ * S_) / 128, 3);
    gemm_qkv<<<qkv_grid, 256, gsmem>>>(b_q, b_k, b_v);

    dim3 agrid(S_ / 128, H_, B_);
    attn_mma<<<agrid, 128, asmem>>>(Qh, Ql, Kh, Kl, Vh, Vl, AOh, AOl);

    dim3 ogrid(D_ / 128, (B_ * S_) / 128);
    gemm_out<<<ogrid, 256, gsmem>>>(b_o, out);
}

// round 11
// speedup vs baseline: 1.2858x; 1.1682x over previous
#include <cuda_runtime.h>
#include <cuda_fp16.h>
#include <stdint.h>

#define B_  2
#define S_  2048
#define D_  1024
#define H_  16
#define DH_ 64
#define NE_ (B_ * S_ * D_)
#define NKB (S_ / 64)
#define NW_ (D_ * D_)

// Scratch (allocation-free): fp16 hi/lo planes packed 2-per-u32.
__device__ uint32_t g_Qh[NE_ / 2], g_Ql[NE_ / 2];   // proj Q, pre-scaled
__device__ uint32_t g_Kh[NE_ / 2], g_Kl[NE_ / 2];   // proj K
__device__ uint32_t g_Vh[NE_ / 2], g_Vl[NE_ / 2];   // proj V transposed [b][h][dh][s]
__device__ uint32_t g_AOh[NE_ / 2], g_AOl[NE_ / 2]; // attention output planes
__device__ uint32_t g_Xqh[NE_ / 2], g_Xql[NE_ / 2];
__device__ uint32_t g_Xkh[NE_ / 2], g_Xkl[NE_ / 2];
__device__ uint32_t g_Xvh[NE_ / 2], g_Xvl[NE_ / 2];
__device__ uint32_t g_Wqh[NW_ / 2];                 // weights: hi plane only
__device__ uint32_t g_Wkh[NW_ / 2];
__device__ uint32_t g_Wvh[NW_ / 2];
__device__ uint32_t g_Woh[NW_ / 2];

// (1/8) * log2(e): folds softmax exp -> exp2
#define QSCALE 0.1803368801111204f

// ---------------------------------------------------------------------------
__device__ __forceinline__ void split2(float x, float y, uint32_t& hi, uint32_t& lo)
{
    __half2 h = __floats2half2_rn(x, y);
    float rx = x - __half2float(__low2half(h));
    float ry = y - __half2float(__high2half(h));
    __half2 l = __floats2half2_rn(rx, ry);
    hi = *reinterpret_cast<uint32_t*>(&h);
    lo = *reinterpret_cast<uint32_t*>(&l);
}

__device__ __forceinline__ uint32_t pack_hi(float x, float y)
{
    __half2 h = __floats2half2_rn(x, y);
    return *reinterpret_cast<uint32_t*>(&h);
}

__device__ __forceinline__ void mma_fp16(float4& d,
    uint32_t a0, uint32_t a1, uint32_t a2, uint32_t a3,
    uint32_t b0, uint32_t b1)
{
    asm volatile(
        "mma.sync.aligned.m16n8k16.row.col.f32.f16.f16.f32 "
        "{%0,%1,%2,%3},{%4,%5,%6,%7},{%8,%9},{%0,%1,%2,%3};"
        : "+f"(d.x), "+f"(d.y), "+f"(d.z), "+f"(d.w)
        : "r"(a0), "r"(a1), "r"(a2), "r"(a3), "r"(b0), "r"(b1));
}

__device__ __forceinline__ void ldsm_x4(uint32_t& r0, uint32_t& r1,
                                        uint32_t& r2, uint32_t& r3, uint32_t addr)
{
    asm volatile("ldmatrix.sync.aligned.m8n8.x4.shared.b16 {%0,%1,%2,%3}, [%4];"
                 : "=r"(r0), "=r"(r1), "=r"(r2), "=r"(r3) : "r"(addr));
}

__device__ __forceinline__ void cp16(uint32_t smaddr, const void* g)
{
    asm volatile("cp.async.cg.shared.global [%0], [%1], 16;" :: "r"(smaddr), "l"(g));
}
__device__ __forceinline__ void cp_commit()
{
    asm volatile("cp.async.commit_group;" ::: "memory");
}

// ---------------------------------------------------------------------------
// ONE fused split pass. Activations: hi+lo planes. Weights: hi plane only.
// ---------------------------------------------------------------------------
__global__ __launch_bounds__(256) void split_all(
    const float* __restrict__ q, const float* __restrict__ k, const float* __restrict__ v,
    const float* __restrict__ wq, const float* __restrict__ wk,
    const float* __restrict__ wv, const float* __restrict__ wo)
{
    const int bid = blockIdx.x;
    if (bid < 12288) {
        int seg = bid >> 12;
        int i = (bid & 4095) * 256 + threadIdx.x;
        const float* src;
        uint32_t *hi, *lo;
        if (seg == 0)      { src = q; hi = g_Xqh; lo = g_Xql; }
        else if (seg == 1) { src = k; hi = g_Xkh; lo = g_Xkl; }
        else               { src = v; hi = g_Xvh; lo = g_Xvl; }
        float4 val = ((const float4*)src)[i];
        uint32_t h0, l0, h1, l1;
        split2(val.x, val.y, h0, l0);
        split2(val.z, val.w, h1, l1);
        ((uint2*)hi)[i] = make_uint2(h0, h1);
        ((uint2*)lo)[i] = make_uint2(l0, l1);
    } else {
        int seg = (bid - 12288) >> 10;
        int i = ((bid - 12288) & 1023) * 256 + threadIdx.x;
        const float* src;
        uint32_t* hi;
        if (seg == 0)      { src = wq; hi = g_Wqh; }
        else if (seg == 1) { src = wk; hi = g_Wkh; }
        else if (seg == 2) { src = wv; hi = g_Wvh; }
        else               { src = wo; hi = g_Woh; }
        float4 val = ((const float4*)src)[i];
        ((uint2*)hi)[i] = make_uint2(pack_hi(val.x, val.y), pack_hi(val.z, val.w));
    }
}

// ---------------------------------------------------------------------------
// fp16x2 GEMM core: C = (A_hi + A_lo) @ W_hi^T + bias  (2 MMA terms).
// BM=128, BN=128, BK=32, 2 stages, one sync/iter, 8 warps, warp tile 32x64.
// Stage: 3 planes x 128 rows x 20 u32 = 7680 u32; dyn smem 2x30720 = 61440 B.
// ---------------------------------------------------------------------------
#define GSTG   7680u
#define GA_LO  2560u
#define GW_HI  5120u

__device__ __forceinline__ void gemm_core(
    const uint32_t* __restrict__ Ah, const uint32_t* __restrict__ Al,
    const uint32_t* __restrict__ Wh,
    const float* __restrict__ bias,
    float* __restrict__ Cf, uint32_t* __restrict__ Ch, uint32_t* __restrict__ Cl,
    int mode, uint32_t sb)
{
    const int tid  = threadIdx.x;
    const int lane = tid & 31;
    const int wid  = tid >> 5;
    const int wm   = wid & 3;
    const int wn   = wid >> 2;
    const int r    = lane >> 2;
    const int c    = lane & 3;

    const int m_base = blockIdx.y * 128;
    const int n_base = blockIdx.x * 128;
    const int KW = D_ >> 1;

    const int lrA = (lane & 7) + (((lane >> 3) & 1) << 3);
    const int lcA = (lane >> 4) * 4;
    const int lrB = (lane & 7) + ((lane >> 4) << 3);
    const int lcB = ((lane >> 3) & 1) * 4;

    auto prefetch = [&](int ktile) {
        uint32_t base = sb + (uint32_t)(ktile & 1) * GSTG * 4u;
        int ktw = ktile * 16;
#pragma unroll
        for (int t = 0; t < 2; t++) {
            int idx = tid + t * 256;
            int row = idx >> 2, cg = (idx & 3) * 4;
            uint32_t so = (uint32_t)(row * 20 + cg) * 4u;
            size_t ga = (size_t)(m_base + row) * KW + ktw + cg;
            size_t gw = (size_t)(n_base + row) * KW + ktw + cg;
            cp16(base + so,                Ah + ga);
            cp16(base + GA_LO * 4u + so,   Al + ga);
            cp16(base + GW_HI * 4u + so,   Wh + gw);
        }
        cp_commit();
    };

    float4 acc[2][8];
#pragma unroll
    for (int i = 0; i < 2; i++)
#pragma unroll
        for (int j = 0; j < 8; j++) acc[i][j] = make_float4(0.f, 0.f, 0.f, 0.f);

    const int NT = D_ / 32;
    prefetch(0);

    for (int kt = 0; kt < NT; kt++) {
        asm volatile("cp.async.wait_group 0;" ::: "memory");
        __syncthreads();
        if (kt + 1 < NT) prefetch(kt + 1);

        uint32_t base = sb + (uint32_t)(kt & 1) * GSTG * 4u;

#pragma unroll
        for (int ks = 0; ks < 2; ks++) {
            uint32_t ah[2][4], al[2][4];
#pragma unroll
            for (int mt = 0; mt < 2; mt++) {
                uint32_t o = (uint32_t)((wm * 32 + mt * 16 + lrA) * 20 + ks * 8 + lcA) * 4u;
                ldsm_x4(ah[mt][0], ah[mt][1], ah[mt][2], ah[mt][3], base + o);
                ldsm_x4(al[mt][0], al[mt][1], al[mt][2], al[mt][3], base + GA_LO * 4u + o);
            }
            uint32_t bh[4][4];
#pragma unroll
            for (int ntp = 0; ntp < 4; ntp++) {
                uint32_t o = (uint32_t)((wn * 64 + ntp * 16 + lrB) * 20 + ks * 8 + lcB) * 4u;
                ldsm_x4(bh[ntp][0], bh[ntp][1], bh[ntp][2], bh[ntp][3], base + GW_HI * 4u + o);
            }
            // term hh
#pragma unroll
            for (int ntp = 0; ntp < 4; ntp++)
#pragma unroll
                for (int mt = 0; mt < 2; mt++) {
                    mma_fp16(acc[mt][2 * ntp],     ah[mt][0], ah[mt][1], ah[mt][2], ah[mt][3], bh[ntp][0], bh[ntp][1]);
                    mma_fp16(acc[mt][2 * ntp + 1], ah[mt][0], ah[mt][1], ah[mt][2], ah[mt][3], bh[ntp][2], bh[ntp][3]);
                }
            // term lh
#pragma unroll
            for (int ntp = 0; ntp < 4; ntp++)
#pragma unroll
                for (int mt = 0; mt < 2; mt++) {
                    mma_fp16(acc[mt][2 * ntp],     al[mt][0], al[mt][1], al[mt][2], al[mt][3], bh[ntp][0], bh[ntp][1]);
                    mma_fp16(acc[mt][2 * ntp + 1], al[mt][0], al[mt][1], al[mt][2], al[mt][3], bh[ntp][2], bh[ntp][3]);
                }
        }
    }

    // epilogue
#pragma unroll
    for (int mt = 0; mt < 2; mt++) {
#pragma unroll
        for (int nt = 0; nt < 8; nt++) {
            int gm0 = m_base + wm * 32 + mt * 16 + r;
            int gm1 = gm0 + 8;
            int gn  = n_base + wn * 64 + nt * 8 + c * 2;
            float b0v = bias[gn], b1v = bias[gn + 1];
            float f00 = acc[mt][nt].x + b0v, f01 = acc[mt][nt].y + b1v;
            float f10 = acc[mt][nt].z + b0v, f11 = acc[mt][nt].w + b1v;
            if (mode == 1) { f00 *= QSCALE; f01 *= QSCALE; f10 *= QSCALE; f11 *= QSCALE; }

            if (mode == 0) {
                *(float2*)(Cf + (size_t)gm0 * D_ + gn) = make_float2(f00, f01);
                *(float2*)(Cf + (size_t)gm1 * D_ + gn) = make_float2(f10, f11);
            } else if (mode == 1 || mode == 2) {
                uint32_t h0, l0, h1, l1;
                split2(f00, f01, h0, l0);
                split2(f10, f11, h1, l1);
                Ch[(size_t)gm0 * 512 + gn / 2] = h0;
                Cl[(size_t)gm0 * 512 + gn / 2] = l0;
                Ch[(size_t)gm1 * 512 + gn / 2] = h1;
                Cl[(size_t)gm1 * 512 + gn / 2] = l1;
            } else {
                __half* Chb = (__half*)Ch;
                __half* Clb = (__half*)Cl;
                float fv[2][2] = {{f00, f01}, {f10, f11}};
                int gms[2] = {gm0, gm1};
#pragma unroll
                for (int i = 0; i < 2; i++)
#pragma unroll
                    for (int j = 0; j < 2; j++) {
                        int m = gms[i], n = gn + j;
                        int bb = m >> 11, s = m & 2047;
                        int hh = n >> 6, dh = n & 63;
                        size_t idx = (((size_t)(bb * H_ + hh) * DH_ + dh) * S_) + s;
                        __half hv = __float2half_rn(fv[i][j]);
                        Chb[idx] = hv;
                        Clb[idx] = __float2half_rn(fv[i][j] - __half2float(hv));
                    }
            }
        }
    }
}

__global__ __launch_bounds__(256, 2) void gemm_qkv(
    const float* __restrict__ b_q, const float* __restrict__ b_k,
    const float* __restrict__ b_v)
{
    extern __shared__ uint32_t sg[];
    const uint32_t sb = (uint32_t)__cvta_generic_to_shared(sg);
    const int z = blockIdx.z;
    if (z == 0)
        gemm_core(g_Xqh, g_Xql, g_Wqh, b_q, nullptr, g_Qh, g_Ql, 1, sb);
    else if (z == 1)
        gemm_core(g_Xkh, g_Xkl, g_Wkh, b_k, nullptr, g_Kh, g_Kl, 2, sb);
    else
        gemm_core(g_Xvh, g_Xvl, g_Wvh, b_v, nullptr, g_Vh, g_Vl, 3, sb);
}

__global__ __launch_bounds__(256, 2) void gemm_out(
    const float* __restrict__ b_o, float* __restrict__ out)
{
    extern __shared__ uint32_t sg[];
    const uint32_t sb = (uint32_t)__cvta_generic_to_shared(sg);
    gemm_core(g_AOh, g_AOl, g_Woh, b_o, out, nullptr, nullptr, 0, sb);
}

// ---------------------------------------------------------------------------
// Flash attention, mma fp16x3 (all 3 terms kept), exp2 softmax.
// 2-stage cp.async, one sync/block, 4 warps, 32 q-rows/warp.
// Dyn smem: 2 x 4 planes x 64 x 36 u32 = 73728 B (2 CTAs/SM).
// ---------------------------------------------------------------------------
__global__ __launch_bounds__(128, 2) void attn_mma(
    const uint32_t* __restrict__ Qh, const uint32_t* __restrict__ Ql,
    const uint32_t* __restrict__ Kh, const uint32_t* __restrict__ Kl,
    const uint32_t* __restrict__ Vh, const uint32_t* __restrict__ Vl,
    uint32_t* __restrict__ AOh, uint32_t* __restrict__ AOl)
{
    extern __shared__ uint32_t smu[];
    const int tid  = threadIdx.x;
    const int lane = tid & 31;
    const int wid  = tid >> 5;
    const int r    = lane >> 2;
    const int c    = lane & 3;
    const int h    = blockIdx.y;
    const int b    = blockIdx.z;
    const int q0   = blockIdx.x * 128 + wid * 32;

    const size_t qk_base = ((size_t)b * S_ * D_ + h * DH_) / 2;
    const size_t v_base  = ((size_t)(b * H_ + h) * DH_ * S_) / 2;
    const uint32_t* Qh32 = Qh + qk_base;
    const uint32_t* Ql32 = Ql + qk_base;
    const uint32_t* Kh32 = Kh + qk_base;
    const uint32_t* Kl32 = Kl + qk_base;
    const uint32_t* Vh32 = Vh + v_base;
    const uint32_t* Vl32 = Vl + v_base;

    const uint32_t sbase = (uint32_t)__cvta_generic_to_shared(smu);
    const int lr  = (lane & 7) + ((lane >> 4) << 3);
    const int lc4 = ((lane >> 3) & 1) * 4;
    const uint32_t laddr = (uint32_t)(lr * 36 + lc4) * 4;

    uint32_t qh[2][4][4], ql[2][4][4];
#pragma unroll
    for (int mt = 0; mt < 2; mt++) {
        int rb = q0 + mt * 16;
#pragma unroll
        for (int kt = 0; kt < 4; kt++) {
            qh[mt][kt][0] = Qh32[(size_t)(rb + r) * 512 + kt * 8 + c];
            qh[mt][kt][1] = Qh32[(size_t)(rb + 8 + r) * 512 + kt * 8 + c];
            qh[mt][kt][2] = Qh32[(size_t)(rb + r) * 512 + kt * 8 + c + 4];
            qh[mt][kt][3] = Qh32[(size_t)(rb + 8 + r) * 512 + kt * 8 + c + 4];
            ql[mt][kt][0] = Ql32[(size_t)(rb + r) * 512 + kt * 8 + c];
            ql[mt][kt][1] = Ql32[(size_t)(rb + 8 + r) * 512 + kt * 8 + c];
            ql[mt][kt][2] = Ql32[(size_t)(rb + r) * 512 + kt * 8 + c + 4];
            ql[mt][kt][3] = Ql32[(size_t)(rb + 8 + r) * 512 + kt * 8 + c + 4];
        }
    }

    float4 oacc[2][8];
#pragma unroll
    for (int mt = 0; mt < 2; mt++)
#pragma unroll
        for (int j = 0; j < 8; j++) oacc[mt][j] = make_float4(0.f, 0.f, 0.f, 0.f);
    float mi[2][2], li[2][2];
#pragma unroll
    for (int mt = 0; mt < 2; mt++) { mi[mt][0] = mi[mt][1] = -1e30f; li[mt][0] = li[mt][1] = 0.f; }

    auto prefetch = [&](int kb) {
        uint32_t bufb = sbase + (uint32_t)(kb & 1) * 9216 * 4;
#pragma unroll
        for (int t = 0; t < 4; t++) {
            int i = tid + t * 128;
            int row = i >> 3, col = (i & 7) * 4;
            uint32_t off = (uint32_t)(row * 36 + col) * 4;
            size_t kg = (size_t)(kb * 64 + row) * 512 + col;
            size_t vg = (size_t)row * 1024 + kb * 32 + col;
            cp16(bufb + off,            Kh32 + kg);
            cp16(bufb + 2304 * 4 + off, Kl32 + kg);
            cp16(bufb + 4608 * 4 + off, Vh32 + vg);
            cp16(bufb + 6912 * 4 + off, Vl32 + vg);
        }
        cp_commit();
    };

    prefetch(0);

    for (int kb = 0; kb < NKB; kb++) {
        asm volatile("cp.async.wait_group 0;" ::: "memory");
        __syncthreads();
        if (kb + 1 < NKB) prefetch(kb + 1);

        uint32_t bufb = sbase + (uint32_t)(kb & 1) * 9216 * 4;
        uint32_t kh_b = bufb, kl_b = bufb + 2304 * 4;
        uint32_t vh_b = bufb + 4608 * 4, vl_b = bufb + 6912 * 4;

        float4 sacc[2][8];
#pragma unroll
        for (int mt = 0; mt < 2; mt++)
#pragma unroll
            for (int nt = 0; nt < 8; nt++) sacc[mt][nt] = make_float4(0.f, 0.f, 0.f, 0.f);
#pragma unroll
        for (int ng = 0; ng < 4; ng++) {
#pragma unroll
            for (int kt = 0; kt < 4; kt++) {
                uint32_t o = laddr + (uint32_t)(ng * 576 + kt * 8) * 4;
                uint32_t h0, h1, h2, h3, l0, l1, l2, l3;
                ldsm_x4(h0, h1, h2, h3, kh_b + o);
                ldsm_x4(l0, l1, l2, l3, kl_b + o);
#pragma unroll
                for (int mt = 0; mt < 2; mt++) {
                    mma_fp16(sacc[mt][2 * ng],     qh[mt][kt][0], qh[mt][kt][1], qh[mt][kt][2], qh[mt][kt][3], h0, h1);
                    mma_fp16(sacc[mt][2 * ng + 1], qh[mt][kt][0], qh[mt][kt][1], qh[mt][kt][2], qh[mt][kt][3], h2, h3);
                }
#pragma unroll
                for (int mt = 0; mt < 2; mt++) {
                    mma_fp16(sacc[mt][2 * ng],     qh[mt][kt][0], qh[mt][kt][1], qh[mt][kt][2], qh[mt][kt][3], l0, l1);
                    mma_fp16(sacc[mt][2 * ng + 1], qh[mt][kt][0], qh[mt][kt][1], qh[mt][kt][2], qh[mt][kt][3], l2, l3);
                }
#pragma unroll
                for (int mt = 0; mt < 2; mt++) {
                    mma_fp16(sacc[mt][2 * ng],     ql[mt][kt][0], ql[mt][kt][1], ql[mt][kt][2], ql[mt][kt][3], h0, h1);
                    mma_fp16(sacc[mt][2 * ng + 1], ql[mt][kt][0], ql[mt][kt][1], ql[mt][kt][2], ql[mt][kt][3], h2, h3);
                }
            }
        }

        uint32_t ph[2][4][4], pl[2][4][4];
#pragma unroll
        for (int mt = 0; mt < 2; mt++) {
            float m0 = -1e30f, m1 = -1e30f;
#pragma unroll
            for (int nt = 0; nt < 8; nt++) {
                m0 = fmaxf(m0, fmaxf(sacc[mt][nt].x, sacc[mt][nt].y));
                m1 = fmaxf(m1, fmaxf(sacc[mt][nt].z, sacc[mt][nt].w));
            }
#pragma unroll
            for (int o = 1; o <= 2; o <<= 1) {
                m0 = fmaxf(m0, __shfl_xor_sync(0xffffffffu, m0, o));
                m1 = fmaxf(m1, __shfl_xor_sync(0xffffffffu, m1, o));
            }
            float mn0 = fmaxf(mi[mt][0], m0), mn1 = fmaxf(mi[mt][1], m1);
            float corr0 = exp2f(mi[mt][0] - mn0), corr1 = exp2f(mi[mt][1] - mn1);
            float rs0 = 0.f, rs1 = 0.f;
#pragma unroll
            for (int nt = 0; nt < 8; nt++) {
                sacc[mt][nt].x = exp2f(sacc[mt][nt].x - mn0);
                sacc[mt][nt].y = exp2f(sacc[mt][nt].y - mn0);
                sacc[mt][nt].z = exp2f(sacc[mt][nt].z - mn1);
                sacc[mt][nt].w = exp2f(sacc[mt][nt].w - mn1);
                rs0 += sacc[mt][nt].x + sacc[mt][nt].y;
                rs1 += sacc[mt][nt].z + sacc[mt][nt].w;
            }
#pragma unroll
            for (int o = 1; o <= 2; o <<= 1) {
                rs0 += __shfl_xor_sync(0xffffffffu, rs0, o);
                rs1 += __shfl_xor_sync(0xffffffffu, rs1, o);
            }
            li[mt][0] = li[mt][0] * corr0 + rs0;
            li[mt][1] = li[mt][1] * corr1 + rs1;
            mi[mt][0] = mn0; mi[mt][1] = mn1;
#pragma unroll
            for (int j = 0; j < 8; j++) {
                oacc[mt][j].x *= corr0; oacc[mt][j].y *= corr0;
                oacc[mt][j].z *= corr1; oacc[mt][j].w *= corr1;
            }
#pragma unroll
            for (int t = 0; t < 4; t++) {
                split2(sacc[mt][2 * t].x,     sacc[mt][2 * t].y,     ph[mt][t][0], pl[mt][t][0]);
                split2(sacc[mt][2 * t].z,     sacc[mt][2 * t].w,     ph[mt][t][1], pl[mt][t][1]);
                split2(sacc[mt][2 * t + 1].x, sacc[mt][2 * t + 1].y, ph[mt][t][2], pl[mt][t][2]);
                split2(sacc[mt][2 * t + 1].z, sacc[mt][2 * t + 1].w, ph[mt][t][3], pl[mt][t][3]);
            }
        }

#pragma unroll
        for (int jg = 0; jg < 4; jg++) {
#pragma unroll
            for (int kt = 0; kt < 4; kt++) {
                uint32_t o = laddr + (uint32_t)(jg * 576 + kt * 8) * 4;
                uint32_t h0, h1, h2, h3, l0, l1, l2, l3;
                ldsm_x4(h0, h1, h2, h3, vh_b + o);
                ldsm_x4(l0, l1, l2, l3, vl_b + o);
#pragma unroll
                for (int mt = 0; mt < 2; mt++) {
                    mma_fp16(oacc[mt][2 * jg],     ph[mt][kt][0], ph[mt][kt][1], ph[mt][kt][2], ph[mt][kt][3], h0, h1);
                    mma_fp16(oacc[mt][2 * jg + 1], ph[mt][kt][0], ph[mt][kt][1], ph[mt][kt][2], ph[mt][kt][3], h2, h3);
                }
#pragma unroll
                for (int mt = 0; mt < 2; mt++) {
                    mma_fp16(oacc[mt][2 * jg],     ph[mt][kt][0], ph[mt][kt][1], ph[mt][kt][2], ph[mt][kt][3], l0, l1);
                    mma_fp16(oacc[mt][2 * jg + 1], ph[mt][kt][0], ph[mt][kt][1], ph[mt][kt][2], ph[mt][kt][3], l2, l3);
                }
#pragma unroll
                for (int mt = 0; mt < 2; mt++) {
                    mma_fp16(oacc[mt][2 * jg],     pl[mt][kt][0], pl[mt][kt][1], pl[mt][kt][2], pl[mt][kt][3], h0, h1);
                    mma_fp16(oacc[mt][2 * jg + 1], pl[mt][kt][0], pl[mt][kt][1], pl[mt][kt][2], pl[mt][kt][3], h2, h3);
                }
            }
        }
    }

#pragma unroll
    for (int mt = 0; mt < 2; mt++) {
        float inv0 = 1.f / li[mt][0], inv1 = 1.f / li[mt][1];
        const size_t row0 = ((size_t)b * S_ + q0 + mt * 16 + r) * 512;
        const size_t row1 = row0 + 8 * 512;
#pragma unroll
        for (int j = 0; j < 8; j++) {
            int w = h * 32 + j * 4 + c;
            uint32_t hw, lw;
            split2(oacc[mt][j].x * inv0, oacc[mt][j].y * inv0, hw, lw);
            AOh[row0 + w] = hw; AOl[row0 + w] = lw;
            split2(oacc[mt][j].z * inv1, oacc[mt][j].w * inv1, hw, lw);
            AOh[row1 + w] = hw; AOl[row1 + w] = lw;
        }
    }
}

// ---------------------------------------------------------------------------
extern "C" void kernel_launch(void* const* d_in, const int* in_sizes, int n_in,
                              void* d_out, int out_size)
{
    const float* queries = (const float*)d_in[0];
    const float* keys    = (const float*)d_in[1];
    const float* values  = (const float*)d_in[2];
    const float* W_q = (const float*)d_in[3];
    const float* b_q = (const float*)d_in[4];
    const float* W_k = (const float*)d_in[5];
    const float* b_k = (const float*)d_in[6];
    const float* W_v = (const float*)d_in[7];
    const float* b_v = (const float*)d_in[8];
    const float* W_o = (const float*)d_in[9];
    const float* b_o = (const float*)d_in[10];
    float* out = (float*)d_out;

    uint32_t *Qh, *Ql, *Kh, *Kl, *Vh, *Vl, *AOh, *AOl;
    cudaGetSymbolAddress((void**)&Qh, g_Qh);
    cudaGetSymbolAddress((void**)&Ql, g_Ql);
    cudaGetSymbolAddress((void**)&Kh, g_Kh);
    cudaGetSymbolAddress((void**)&Kl, g_Kl);
    cudaGetSymbolAddress((void**)&Vh, g_Vh);
    cudaGetSymbolAddress((void**)&Vl, g_Vl);
    cudaGetSymbolAddress((void**)&AOh, g_AOh);
    cudaGetSymbolAddress((void**)&AOl, g_AOl);

    const int gsmem = 2 * GSTG * 4;   // 61440
    cudaFuncSetAttribute(gemm_qkv, cudaFuncAttributeMaxDynamicSharedMemorySize, gsmem);
    cudaFuncSetAttribute(gemm_out, cudaFuncAttributeMaxDynamicSharedMemorySize, gsmem);
    const int asmem = 2 * 9216 * 4;   // 73728
    cudaFuncSetAttribute(attn_mma, cudaFuncAttributeMaxDynamicSharedMemorySize, asmem);

    split_all<<<16384, 256>>>(queries, keys, values, W_q, W_k, W_v, W_o);

    dim3 qkv_grid(D_ / 128, (B_ * S_) / 128, 3);
    gemm_qkv<<<qkv_grid, 256, gsmem>>>(b_q, b_k, b_v);

    dim3 agrid(S_ / 128, H_, B_);
    attn_mma<<<agrid, 128, asmem>>>(Qh, Ql, Kh, Kl, Vh, Vl, AOh, AOl);

    dim3 ogrid(D_ / 128, (B_ * S_) / 128);
    gemm_out<<<ogrid, 256, gsmem>>>(b_o, out);
}